// round 12
// baseline (speedup 1.0000x reference)
#include <cuda_runtime.h>
#include <cstdint>

#define BB 4
#define NPTS 20000
#define CC 512
#define MM 1024
#define GRASP_TH 0.1f

#define FPS_THREADS 512
#define FPS_WARPS (FPS_THREADS / 32)   // 16
#define CAPR 10                        // register-resident points per thread
#define PAIRS (CAPR / 2)
#define REGN (FPS_THREADS * CAPR)      // 5120 register-resident points

// ---------------- scratch (static device allocations; no cudaMalloc) -------
__device__ float4 g_cp[BB * NPTS];    // compacted xyz (compaction order = index order)
__device__ int    g_cidx[BB * NPTS];  // compacted -> original index
__device__ float  g_mind[BB * NPTS];  // FPS min-dist (gmem fallback region only)
__device__ int    g_fps[BB * MM];     // sampled original indices
__device__ int    g_nn[BB * MM * 3];  // 3-NN indices
__device__ float  g_w[BB * MM * 3];   // normalized IDW weights
__device__ float4 g_pc4[BB * NPTS];   // full cloud packed as float4

__device__ __forceinline__ float finf()  { return __int_as_float(0x7f800000); }

// packed f32x2 helpers (Blackwell sm_103a; per-component IEEE rn => bit-exact)
#define ADD2(out, a, b) asm("add.rn.f32x2 %0, %1, %2;" : "=l"(out) : "l"(a), "l"(b))
#define MUL2(out, a, b) asm("mul.rn.f32x2 %0, %1, %2;" : "=l"(out) : "l"(a), "l"(b))
#define PACK2(out, lo, hi) asm("mov.b64 %0, {%1, %2};" : "=l"(out) : "r"(lo), "r"(hi))
#define UNPACK2(lo, hi, in) asm("mov.b64 {%0, %1}, %2;" : "=r"(lo), "=r"(hi) : "l"(in))

// ============================================================================
// Kernel 0: pack full cloud into float4 for LDS.128 in nn_kernel
// ============================================================================
__global__ __launch_bounds__(256)
void pack_kernel(const float* __restrict__ pc)
{
    int e = blockIdx.x * 256 + threadIdx.x;
    if (e < BB * NPTS) {
        const float* p = pc + (size_t)e * 3;
        g_pc4[e] = make_float4(p[0], p[1], p[2], 0.0f);
    }
}

// ============================================================================
// Kernel 1: per-batch mask compaction + furthest point sampling.
// Hot loop = EXACT R6 (proven 611us): packed f32x2 distances + inline
// (bV,bI) tracking with strict > (ascending k => lowest index kept).
// Stage-1 tail REPLACED: candidate lanes fire ONE fire-and-forget
// atomicMax on a per-warp u64 slot packing
//   (it<<47) | (distBits<<15) | (0x7fff ^ idx)
// -- monotone iteration tag (no resets needed), exact f32 value bits,
// inverted index => u64 max == (max value, min index). Double-buffered
// slots + the barrier make stale overwrites provably impossible.
// Distance bit-exact vs XLA: no FMA, ((dx*dx + dy*dy) + dz*dz), rn.
// ============================================================================
__global__ __launch_bounds__(FPS_THREADS, 1)
void fps_kernel(const float* __restrict__ pc,
                const float* __restrict__ obj,
                const float* __restrict__ gr)
{
    const int b    = blockIdx.x;
    const int tid  = threadIdx.x;
    const int lane = tid & 31;
    const int wid  = tid >> 5;

    __shared__ int s_wsum[FPS_WARPS];
    __shared__ int s_base;
    __shared__ unsigned long long s_vi[2][FPS_WARPS];  // tagged packed entries

    if (tid == 0) s_base = 0;
    __syncthreads();

    const float* objb = obj + (size_t)b * 2 * NPTS;
    const float* grb  = gr  + (size_t)b * NPTS;
    const float* pcb  = pc  + (size_t)b * NPTS * 3;

    // ---- order-preserving compaction of masked points ----
    for (int start = 0; start < NPTS; start += FPS_THREADS) {
        int i = start + tid;
        bool p = false;
        if (i < NPTS)
            p = (objb[NPTS + i] > objb[i]) && (grb[i] > GRASP_TH);
        unsigned bal = __ballot_sync(0xffffffffu, p);
        int wcnt = __popc(bal);
        int wpre = __popc(bal & ((1u << lane) - 1u));
        if (lane == 0) s_wsum[wid] = wcnt;
        __syncthreads();
        if (tid == 0) {
            int acc = s_base;
            #pragma unroll
            for (int w = 0; w < FPS_WARPS; ++w) { int c = s_wsum[w]; s_wsum[w] = acc; acc += c; }
            s_base = acc;
        }
        __syncthreads();
        if (p) {
            int pos = s_wsum[wid] + wpre;
            g_cidx[b * NPTS + pos] = i;
            float4 q;
            q.x = pcb[3 * i]; q.y = pcb[3 * i + 1]; q.z = pcb[3 * i + 2]; q.w = 0.0f;
            g_cp[b * NPTS + pos] = q;
        }
        __syncthreads();
    }
    const int cnt = s_base;

    if (cnt == 0) {
        for (int j = tid; j < MM; j += FPS_THREADS) g_fps[b * MM + j] = 0;
        return;
    }

    const float4* cp = g_cp + b * NPTS;
    const int regCnt = min(cnt, REGN);
    const bool havefb = (cnt > REGN);

    // ---- load owned points into packed registers (R6 layout) ----
    unsigned long long rx2[PAIRS], ry2[PAIRS], rz2[PAIRS];
    float md[CAPR];
    #pragma unroll
    for (int p = 0; p < PAIRS; ++p) {
        float c[2][3];
        #pragma unroll
        for (int h = 0; h < 2; ++h) {
            const int k = 2 * p + h;
            const int i = tid + k * FPS_THREADS;
            if (i < regCnt) {
                float4 q = cp[i];
                c[h][0] = q.x; c[h][1] = q.y; c[h][2] = q.z;
                md[k] = finf();
            } else {
                c[h][0] = 0.f; c[h][1] = 0.f; c[h][2] = 0.f;
                md[k] = -0.0f;   // -0: never beats bV>=+0 under strict >
            }
        }
        PACK2(rx2[p], __float_as_uint(c[0][0]), __float_as_uint(c[1][0]));
        PACK2(ry2[p], __float_as_uint(c[0][1]), __float_as_uint(c[1][1]));
        PACK2(rz2[p], __float_as_uint(c[0][2]), __float_as_uint(c[1][2]));
    }

    // fallback region (cnt > 5120): gmem state
    float* gmind = g_mind + b * NPTS;
    for (int i = REGN + tid; i < cnt; i += FPS_THREADS) gmind[i] = finf();

    // zero exchange slots (tag 0 < any it >= 1, atomicMax overwrites)
    if (tid < FPS_WARPS) { s_vi[0][tid] = 0ull; s_vi[1][tid] = 0ull; }
    __syncthreads();

    // ---- first pick = compacted point 0 ----
    float4 p0 = cp[0];
    float lx = p0.x, ly = p0.y, lz = p0.z;
    if (tid == 0) g_fps[b * MM] = g_cidx[b * NPTS];

    for (int it = 1; it < MM; ++it) {
        const unsigned ph = (unsigned)(it - 1) & 1u;

        unsigned long long nlx2, nly2, nlz2;
        {
            unsigned nx = __float_as_uint(-lx);
            unsigned ny = __float_as_uint(-ly);
            unsigned nz = __float_as_uint(-lz);
            PACK2(nlx2, nx, nx);
            PACK2(nly2, ny, ny);
            PACK2(nlz2, nz, nz);
        }

        // --- hot loop: EXACT R6 (packed distances + inline bV/bI) ---
        float    bV = 0.0f;
        unsigned bI = 0xffffffffu;
        #pragma unroll
        for (int p = 0; p < PAIRS; ++p) {
            unsigned long long dx2, dy2, dz2, s2;
            ADD2(dx2, rx2[p], nlx2);     // dx = rx - lx (exact rn)
            MUL2(dx2, dx2, dx2);
            ADD2(dy2, ry2[p], nly2);
            MUL2(dy2, dy2, dy2);
            ADD2(s2, dx2, dy2);
            ADD2(dz2, rz2[p], nlz2);
            MUL2(dz2, dz2, dz2);
            ADD2(s2, s2, dz2);           // ((dx2+dy2)+dz2) — XLA order
            unsigned dlo, dhi;
            UNPACK2(dlo, dhi, s2);
            const int k0 = 2 * p, k1 = 2 * p + 1;
            float m0 = fminf(md[k0], __uint_as_float(dlo));
            float m1 = fminf(md[k1], __uint_as_float(dhi));
            md[k0] = m0;
            md[k1] = m1;
            if (m0 > bV) { bV = m0; bI = (unsigned)(tid + k0 * FPS_THREADS); }
            if (m1 > bV) { bV = m1; bI = (unsigned)(tid + k1 * FPS_THREADS); }
        }
        // fallback region (cnt > 5120; rare)
        if (havefb) {
            for (int i = REGN + tid; i < cnt; i += FPS_THREADS) {
                float4 q = cp[i];
                float dx = q.x - lx;
                float dy = q.y - ly;
                float dz = q.z - lz;
                float d = __fadd_rn(__fadd_rn(__fmul_rn(dx, dx),
                                              __fmul_rn(dy, dy)),
                                    __fmul_rn(dz, dz));
                float m = fminf(gmind[i], d);
                gmind[i] = m;
                if (m > bV || (m == bV && (unsigned)i < bI)) { bV = m; bI = (unsigned)i; }
            }
        }

        // --- warp max value via REDUX; candidates fire ONE atomicMax ---
        unsigned vb = __float_as_uint(bV);
        unsigned wv = __reduce_max_sync(0xffffffffu, vb);
        if (vb == wv) {
            unsigned long long entry =
                ((unsigned long long)(unsigned)it << 47) |
                ((unsigned long long)wv << 15) |
                (unsigned long long)(0x7fffu ^ (bI & 0x7fffu));
            atomicMax(&s_vi[ph][wid], entry);
        }
        __syncthreads();

        // --- cross-warp argmax over 16 tagged entries (lexicographic u64) ---
        unsigned long long e = s_vi[ph][lane & (FPS_WARPS - 1)];
        unsigned hv = (unsigned)(e >> 32);
        unsigned lv = (unsigned)e;
        unsigned gh = __reduce_max_sync(0xffffffffu, hv);
        unsigned gl = __reduce_max_sync(0xffffffffu, (hv == gh) ? lv : 0u);
        unsigned long long ge = ((unsigned long long)gh << 32) | gl;
        unsigned gval = (unsigned)(ge >> 15);        // exact f32 distance bits
        unsigned gi   = 0x7fffu ^ ((unsigned)ge & 0x7fffu);
        if (gval == 0u) gi = 0u;  // degenerate: all minds zero -> first masked point

        // --- fetch winner coords: broadcast LDG, L1-resident ---
        float4 w = cp[gi];
        lx = w.x; ly = w.y; lz = w.z;

        if (tid == 0) g_fps[b * MM + it] = g_cidx[b * NPTS + (int)gi];
    }
}

// ============================================================================
// Kernel 2: three_nn — warp serves 4 queries; lane loads each tile point once.
// ============================================================================
#define NNQ 4
#define NNT 256
#define NNW (NNT / 32)
#define QPB (NNW * NNQ)    // 32 queries per block
#define NTS 2048

__global__ __launch_bounds__(NNT, 1)
void nn_kernel()
{
    __shared__ float4 s_pts[NTS];

    const int tid  = threadIdx.x;
    const int lane = tid & 31;
    const int wid  = tid >> 5;
    const int b    = blockIdx.x / (MM / QPB);
    const int q0   = blockIdx.x * QPB + wid * NNQ;

    const float4* pc4b = g_pc4 + (size_t)b * NPTS;

    float qx[NNQ], qy[NNQ], qz[NNQ];
    #pragma unroll
    for (int t = 0; t < NNQ; ++t) {
        const float4 qp = pc4b[g_fps[q0 + t]];
        qx[t] = qp.x; qy[t] = qp.y; qz[t] = qp.z;
    }

    float d0[NNQ], d1[NNQ], d2[NNQ];
    int   i0[NNQ], i1[NNQ], i2[NNQ];
    #pragma unroll
    for (int t = 0; t < NNQ; ++t) {
        d0[t] = finf(); d1[t] = finf(); d2[t] = finf();
        i0[t] = -1;     i1[t] = -1;     i2[t] = -1;
    }

    for (int t0 = 0; t0 < NPTS; t0 += NTS) {
        const int ts = min(NTS, NPTS - t0);
        __syncthreads();
        for (int j = tid; j < ts; j += NNT)
            s_pts[j] = pc4b[t0 + j];
        __syncthreads();

        for (int j = lane; j < ts; j += 32) {
            const float4 w = s_pts[j];
            const int gi = t0 + j;
            #pragma unroll
            for (int t = 0; t < NNQ; ++t) {
                float dx = w.x - qx[t];
                float dy = w.y - qy[t];
                float dz = w.z - qz[t];
                float d = fmaf(dz, dz, fmaf(dy, dy, dx * dx));
                if (d < d2[t]) {
                    if (d < d1[t]) {
                        if (d < d0[t]) { d2[t] = d1[t]; i2[t] = i1[t];
                                         d1[t] = d0[t]; i1[t] = i0[t];
                                         d0[t] = d;     i0[t] = gi; }
                        else           { d2[t] = d1[t]; i2[t] = i1[t];
                                         d1[t] = d;     i1[t] = gi; }
                    } else             { d2[t] = d;     i2[t] = gi; }
                }
            }
        }
    }

    #pragma unroll
    for (int t = 0; t < NNQ; ++t) {
        #pragma unroll
        for (int off = 16; off; off >>= 1) {
            float od0 = __shfl_down_sync(0xffffffffu, d0[t], off);
            float od1 = __shfl_down_sync(0xffffffffu, d1[t], off);
            float od2 = __shfl_down_sync(0xffffffffu, d2[t], off);
            int   oi0 = __shfl_down_sync(0xffffffffu, i0[t], off);
            int   oi1 = __shfl_down_sync(0xffffffffu, i1[t], off);
            int   oi2 = __shfl_down_sync(0xffffffffu, i2[t], off);
            #pragma unroll
            for (int k = 0; k < 3; ++k) {
                float d = (k == 0) ? od0 : (k == 1) ? od1 : od2;
                int   i = (k == 0) ? oi0 : (k == 1) ? oi1 : oi2;
                bool l2 = (d < d2[t]) || (d == d2[t] && i < i2[t]);
                if (l2) {
                    bool l1 = (d < d1[t]) || (d == d1[t] && i < i1[t]);
                    if (l1) {
                        bool l0 = (d < d0[t]) || (d == d0[t] && i < i0[t]);
                        if (l0) { d2[t] = d1[t]; i2[t] = i1[t];
                                  d1[t] = d0[t]; i1[t] = i0[t];
                                  d0[t] = d;     i0[t] = i; }
                        else    { d2[t] = d1[t]; i2[t] = i1[t];
                                  d1[t] = d;     i1[t] = i; }
                    } else      { d2[t] = d;     i2[t] = i; }
                }
            }
        }
        if (lane == 0) {
            const int q = q0 + t;
            float e0 = sqrtf(fmaxf(d0[t], 0.0f));
            float e1 = sqrtf(fmaxf(d1[t], 0.0f));
            float e2 = sqrtf(fmaxf(d2[t], 0.0f));
            float w0 = 1.0f / (e0 + 1e-8f);
            float w1 = 1.0f / (e1 + 1e-8f);
            float w2 = 1.0f / (e2 + 1e-8f);
            float s  = __fadd_rn(__fadd_rn(w0, w1), w2);
            g_w[3 * q + 0] = w0 / s;
            g_w[3 * q + 1] = w1 / s;
            g_w[3 * q + 2] = w2 / s;
            g_nn[3 * q + 0] = i0[t];
            g_nn[3 * q + 1] = i1[t];
            g_nn[3 * q + 2] = i2[t];
        }
    }
}

// ============================================================================
// Kernel 3: IDW feature interpolation.
// ============================================================================
__global__ __launch_bounds__(256)
void interp_kernel(const float* __restrict__ feat, float* __restrict__ out)
{
    int e = blockIdx.x * blockDim.x + threadIdx.x;
    if (e >= BB * CC * MM) return;
    const int m = e % MM;
    const int c = (e / MM) % CC;
    const int b = e / (MM * CC);
    const int q = b * MM + m;

    const int   j0 = g_nn[3 * q],     j1 = g_nn[3 * q + 1], j2 = g_nn[3 * q + 2];
    const float w0 = g_w[3 * q],      w1 = g_w[3 * q + 1],  w2 = g_w[3 * q + 2];
    const float* f = feat + ((size_t)b * CC + c) * NPTS;
    out[e] = w0 * f[j0] + w1 * f[j1] + w2 * f[j2];
}

// ============================================================================
extern "C" void kernel_launch(void* const* d_in, const int* in_sizes, int n_in,
                              void* d_out, int out_size)
{
    const float* pc   = (const float*)d_in[0];  // (B,N,3)
    const float* feat = (const float*)d_in[1];  // (B,C,N)
    const float* obj  = (const float*)d_in[2];  // (B,2,N)
    const float* gr   = (const float*)d_in[3];  // (B,N)
    float* out = (float*)d_out;                 // (B,C,M)

    pack_kernel<<<(BB * NPTS + 255) / 256, 256>>>(pc);
    fps_kernel<<<BB, FPS_THREADS>>>(pc, obj, gr);
    nn_kernel<<<(BB * MM) / QPB, NNT>>>();
    interp_kernel<<<(BB * CC * MM + 255) / 256, 256>>>(feat, out);
}

// round 13
// speedup vs baseline: 1.0517x; 1.0517x over previous
#include <cuda_runtime.h>
#include <cstdint>

#define BB 4
#define NPTS 20000
#define CC 512
#define MM 1024
#define GRASP_TH 0.1f

#define FPS_THREADS 512
#define FPS_WARPS (FPS_THREADS / 32)   // 16
#define CAPR 10                        // register-resident points per thread
#define PAIRS (CAPR / 2)               // 5 packed f32x2 pairs
#define REGN (FPS_THREADS * CAPR)      // 5120 register-resident points

// ---------------- scratch (static device allocations; no cudaMalloc) -------
__device__ float4 g_cp[BB * NPTS];    // compacted xyz
__device__ int    g_cidx[BB * NPTS];  // compacted -> original index
__device__ float  g_mind[BB * NPTS];  // FPS min-dist (gmem fallback region only)
__device__ int    g_fps[BB * MM];     // sampled original indices
__device__ int    g_nn[BB * MM * 3];  // 3-NN indices
__device__ float  g_w[BB * MM * 3];   // normalized IDW weights

__device__ __forceinline__ float finf()  { return __int_as_float(0x7f800000); }

// packed f32x2 helpers (Blackwell sm_103a; per-component IEEE rn => bit-exact)
#define ADD2(out, a, b) asm("add.rn.f32x2 %0, %1, %2;" : "=l"(out) : "l"(a), "l"(b))
#define MUL2(out, a, b) asm("mul.rn.f32x2 %0, %1, %2;" : "=l"(out) : "l"(a), "l"(b))
#define PACK2(out, lo, hi) asm("mov.b64 %0, {%1, %2};" : "=l"(out) : "r"(lo), "r"(hi))
#define UNPACK2(lo, hi, in) asm("mov.b64 {%0, %1}, %2;" : "=r"(lo), "=r"(hi) : "l"(in))

// ============================================================================
// Kernel 1: per-batch mask compaction + furthest point sampling.
// EXACT R6 source (measured 611us) — do not perturb.
// ============================================================================
__global__ __launch_bounds__(FPS_THREADS, 1)
void fps_kernel(const float* __restrict__ pc,
                const float* __restrict__ obj,
                const float* __restrict__ gr)
{
    const int b    = blockIdx.x;
    const int tid  = threadIdx.x;
    const int lane = tid & 31;
    const int wid  = tid >> 5;

    __shared__ int s_wsum[FPS_WARPS];
    __shared__ int s_base;
    __shared__ unsigned long long s_vi[2][FPS_WARPS];  // (valBits<<32) | ~idx

    if (tid == 0) s_base = 0;
    __syncthreads();

    const float* objb = obj + (size_t)b * 2 * NPTS;
    const float* grb  = gr  + (size_t)b * NPTS;
    const float* pcb  = pc  + (size_t)b * NPTS * 3;

    // ---- order-preserving compaction of masked points ----
    for (int start = 0; start < NPTS; start += FPS_THREADS) {
        int i = start + tid;
        bool p = false;
        if (i < NPTS)
            p = (objb[NPTS + i] > objb[i]) && (grb[i] > GRASP_TH);
        unsigned bal = __ballot_sync(0xffffffffu, p);
        int wcnt = __popc(bal);
        int wpre = __popc(bal & ((1u << lane) - 1u));
        if (lane == 0) s_wsum[wid] = wcnt;
        __syncthreads();
        if (tid == 0) {
            int acc = s_base;
            #pragma unroll
            for (int w = 0; w < FPS_WARPS; ++w) { int c = s_wsum[w]; s_wsum[w] = acc; acc += c; }
            s_base = acc;
        }
        __syncthreads();
        if (p) {
            int pos = s_wsum[wid] + wpre;
            g_cidx[b * NPTS + pos] = i;
            float4 q;
            q.x = pcb[3 * i]; q.y = pcb[3 * i + 1]; q.z = pcb[3 * i + 2]; q.w = 0.0f;
            g_cp[b * NPTS + pos] = q;
        }
        __syncthreads();
    }
    const int cnt = s_base;

    if (cnt == 0) {
        for (int j = tid; j < MM; j += FPS_THREADS) g_fps[b * MM + j] = 0;
        return;
    }

    const float4* cp = g_cp + b * NPTS;
    const int regCnt = min(cnt, REGN);

    // ---- load owned points into packed registers ----
    unsigned long long rx2[PAIRS], ry2[PAIRS], rz2[PAIRS];
    float md[CAPR];
    #pragma unroll
    for (int p = 0; p < PAIRS; ++p) {
        const int k0 = 2 * p, k1 = 2 * p + 1;
        int i0 = tid + k0 * FPS_THREADS;
        int i1 = tid + k1 * FPS_THREADS;
        float x0 = 0.f, y0 = 0.f, z0 = 0.f, x1 = 0.f, y1 = 0.f, z1 = 0.f;
        if (i0 < regCnt) { float4 q = cp[i0]; x0 = q.x; y0 = q.y; z0 = q.z; md[k0] = finf(); }
        else               md[k0] = -0.0f;   // -0: never beats bV>=0 under strict >
        if (i1 < regCnt) { float4 q = cp[i1]; x1 = q.x; y1 = q.y; z1 = q.z; md[k1] = finf(); }
        else               md[k1] = -0.0f;
        PACK2(rx2[p], __float_as_uint(x0), __float_as_uint(x1));
        PACK2(ry2[p], __float_as_uint(y0), __float_as_uint(y1));
        PACK2(rz2[p], __float_as_uint(z0), __float_as_uint(z1));
    }

    // fallback region (cnt > 5120): gmem state
    float* gmind = g_mind + b * NPTS;
    for (int i = REGN + tid; i < cnt; i += FPS_THREADS) gmind[i] = finf();
    __syncthreads();

    // ---- first pick = compacted point 0 ----
    float4 p0 = cp[0];
    float lx = p0.x, ly = p0.y, lz = p0.z;
    if (tid == 0) g_fps[b * MM] = g_cidx[b * NPTS];

    for (int it = 1; it < MM; ++it) {
        const unsigned ph = (unsigned)(it - 1) & 1u;

        unsigned long long nlx2, nly2, nlz2;
        {
            unsigned nx = __float_as_uint(-lx);
            unsigned ny = __float_as_uint(-ly);
            unsigned nz = __float_as_uint(-lz);
            PACK2(nlx2, nx, nx);
            PACK2(nly2, ny, ny);
            PACK2(nlz2, nz, nz);
        }

        float    bV = 0.0f;
        unsigned bI = 0xffffffffu;
        #pragma unroll
        for (int p = 0; p < PAIRS; ++p) {
            unsigned long long dx2, dy2, dz2, s2;
            ADD2(dx2, rx2[p], nlx2);     // dx = rx - lx (exact rn)
            MUL2(dx2, dx2, dx2);
            ADD2(dy2, ry2[p], nly2);
            MUL2(dy2, dy2, dy2);
            ADD2(s2, dx2, dy2);
            ADD2(dz2, rz2[p], nlz2);
            MUL2(dz2, dz2, dz2);
            ADD2(s2, s2, dz2);           // (dx*dx + dy*dy) + dz*dz  -- XLA order
            unsigned dlo, dhi;
            UNPACK2(dlo, dhi, s2);
            float m0 = fminf(md[2 * p],     __uint_as_float(dlo));
            float m1 = fminf(md[2 * p + 1], __uint_as_float(dhi));
            md[2 * p]     = m0;
            md[2 * p + 1] = m1;
            if (m0 > bV) { bV = m0; bI = (unsigned)(tid + (2 * p)     * FPS_THREADS); }
            if (m1 > bV) { bV = m1; bI = (unsigned)(tid + (2 * p + 1) * FPS_THREADS); }
        }
        // fallback region (usually empty)
        for (int i = REGN + tid; i < cnt; i += FPS_THREADS) {
            float4 q = cp[i];
            float dx = q.x - lx;
            float dy = q.y - ly;
            float dz = q.z - lz;
            float d = __fadd_rn(__fadd_rn(__fmul_rn(dx, dx),
                                          __fmul_rn(dy, dy)),
                                __fmul_rn(dz, dz));
            float m = fminf(gmind[i], d);
            gmind[i] = m;
            if (m > bV || (m == bV && (unsigned)i < bI)) { bV = m; bI = (unsigned)i; }
        }

        // --- warp argmax via REDUX (bV >= 0 => f32 bits are u32-monotone) ---
        unsigned vb = __float_as_uint(bV);
        unsigned wv = __reduce_max_sync(0xffffffffu, vb);
        unsigned cand = (vb == wv) ? bI : 0xffffffffu;
        unsigned wi = __reduce_min_sync(0xffffffffu, cand);
        if (vb == wv && bI == wi)        // winning lane(s) write identical value
            s_vi[ph][wid] = ((unsigned long long)wv << 32) | (unsigned)(~wi);
        __syncthreads();

        // --- cross-warp argmax over 16 entries, redundantly in every warp ---
        unsigned long long e = s_vi[ph][lane & (FPS_WARPS - 1)];
        unsigned hv = (unsigned)(e >> 32);
        unsigned lv = (unsigned)e;                  // = ~idx
        unsigned gv = __reduce_max_sync(0xffffffffu, hv);
        unsigned cl = (hv == gv) ? lv : 0u;         // max ~idx == min idx
        unsigned gl = __reduce_max_sync(0xffffffffu, cl);
        unsigned gi = ~gl;
        if (gv == 0u) gi = 0u;   // degenerate: all minds zero -> first masked point

        // --- fetch winner coords: broadcast LDG, L1-resident ---
        float4 w = cp[gi];
        lx = w.x; ly = w.y; lz = w.z;

        if (tid == 0) g_fps[b * MM + it] = g_cidx[b * NPTS + (int)gi];
    }
}

// ============================================================================
// Kernel 2: three_nn — warp serves 4 queries; lane loads each tile point once.
// Reads the raw (B,N,3) cloud directly (pack kernel eliminated): tile fill is
// fully coalesced float loads; smem reads are stride-3 scalar (gcd(3,32)=1 =>
// 32 distinct banks, conflict-free).
// ============================================================================
#define NNQ 4
#define NNT 256
#define NNW (NNT / 32)
#define QPB (NNW * NNQ)    // 32 queries per block
#define NTS 2048

__global__ __launch_bounds__(NNT, 1)
void nn_kernel(const float* __restrict__ pc)
{
    __shared__ float s_pts[NTS * 3];

    const int tid  = threadIdx.x;
    const int lane = tid & 31;
    const int wid  = tid >> 5;
    const int b    = blockIdx.x / (MM / QPB);
    const int q0   = blockIdx.x * QPB + wid * NNQ;

    const float* pcb = pc + (size_t)b * NPTS * 3;

    float qx[NNQ], qy[NNQ], qz[NNQ];
    #pragma unroll
    for (int t = 0; t < NNQ; ++t) {
        const int f = g_fps[q0 + t];
        qx[t] = pcb[3 * f];
        qy[t] = pcb[3 * f + 1];
        qz[t] = pcb[3 * f + 2];
    }

    float d0[NNQ], d1[NNQ], d2[NNQ];
    int   i0[NNQ], i1[NNQ], i2[NNQ];
    #pragma unroll
    for (int t = 0; t < NNQ; ++t) {
        d0[t] = finf(); d1[t] = finf(); d2[t] = finf();
        i0[t] = -1;     i1[t] = -1;     i2[t] = -1;
    }

    for (int t0 = 0; t0 < NPTS; t0 += NTS) {
        const int ts = min(NTS, NPTS - t0);
        __syncthreads();
        for (int j = tid; j < ts * 3; j += NNT)
            s_pts[j] = pcb[t0 * 3 + j];
        __syncthreads();

        for (int j = lane; j < ts; j += 32) {
            const float wx = s_pts[3 * j];
            const float wy = s_pts[3 * j + 1];
            const float wz = s_pts[3 * j + 2];
            const int gi = t0 + j;
            #pragma unroll
            for (int t = 0; t < NNQ; ++t) {
                float dx = wx - qx[t];
                float dy = wy - qy[t];
                float dz = wz - qz[t];
                float d = fmaf(dz, dz, fmaf(dy, dy, dx * dx));
                if (d < d2[t]) {
                    if (d < d1[t]) {
                        if (d < d0[t]) { d2[t] = d1[t]; i2[t] = i1[t];
                                         d1[t] = d0[t]; i1[t] = i0[t];
                                         d0[t] = d;     i0[t] = gi; }
                        else           { d2[t] = d1[t]; i2[t] = i1[t];
                                         d1[t] = d;     i1[t] = gi; }
                    } else             { d2[t] = d;     i2[t] = gi; }
                }
            }
        }
    }

    // merge top-3 across the 32 lanes, per query (tie-break: d asc, idx asc)
    #pragma unroll
    for (int t = 0; t < NNQ; ++t) {
        #pragma unroll
        for (int off = 16; off; off >>= 1) {
            float od0 = __shfl_down_sync(0xffffffffu, d0[t], off);
            float od1 = __shfl_down_sync(0xffffffffu, d1[t], off);
            float od2 = __shfl_down_sync(0xffffffffu, d2[t], off);
            int   oi0 = __shfl_down_sync(0xffffffffu, i0[t], off);
            int   oi1 = __shfl_down_sync(0xffffffffu, i1[t], off);
            int   oi2 = __shfl_down_sync(0xffffffffu, i2[t], off);
            #pragma unroll
            for (int k = 0; k < 3; ++k) {
                float d = (k == 0) ? od0 : (k == 1) ? od1 : od2;
                int   i = (k == 0) ? oi0 : (k == 1) ? oi1 : oi2;
                bool l2 = (d < d2[t]) || (d == d2[t] && i < i2[t]);
                if (l2) {
                    bool l1 = (d < d1[t]) || (d == d1[t] && i < i1[t]);
                    if (l1) {
                        bool l0 = (d < d0[t]) || (d == d0[t] && i < i0[t]);
                        if (l0) { d2[t] = d1[t]; i2[t] = i1[t];
                                  d1[t] = d0[t]; i1[t] = i0[t];
                                  d0[t] = d;     i0[t] = i; }
                        else    { d2[t] = d1[t]; i2[t] = i1[t];
                                  d1[t] = d;     i1[t] = i; }
                    } else      { d2[t] = d;     i2[t] = i; }
                }
            }
        }
        if (lane == 0) {
            const int q = q0 + t;
            float e0 = sqrtf(fmaxf(d0[t], 0.0f));
            float e1 = sqrtf(fmaxf(d1[t], 0.0f));
            float e2 = sqrtf(fmaxf(d2[t], 0.0f));
            float w0 = 1.0f / (e0 + 1e-8f);
            float w1 = 1.0f / (e1 + 1e-8f);
            float w2 = 1.0f / (e2 + 1e-8f);
            float s  = __fadd_rn(__fadd_rn(w0, w1), w2);
            g_w[3 * q + 0] = w0 / s;
            g_w[3 * q + 1] = w1 / s;
            g_w[3 * q + 2] = w2 / s;
            g_nn[3 * q + 0] = i0[t];
            g_nn[3 * q + 1] = i1[t];
            g_nn[3 * q + 2] = i2[t];
        }
    }
}

// ============================================================================
// Kernel 3: IDW feature interpolation. out[b,c,m] = sum_k w_k * feat[b,c,nn_k]
// ============================================================================
__global__ __launch_bounds__(256)
void interp_kernel(const float* __restrict__ feat, float* __restrict__ out)
{
    int e = blockIdx.x * blockDim.x + threadIdx.x;
    if (e >= BB * CC * MM) return;
    const int m = e % MM;
    const int c = (e / MM) % CC;
    const int b = e / (MM * CC);
    const int q = b * MM + m;

    const int   j0 = g_nn[3 * q],     j1 = g_nn[3 * q + 1], j2 = g_nn[3 * q + 2];
    const float w0 = g_w[3 * q],      w1 = g_w[3 * q + 1],  w2 = g_w[3 * q + 2];
    const float* f = feat + ((size_t)b * CC + c) * NPTS;
    out[e] = w0 * f[j0] + w1 * f[j1] + w2 * f[j2];
}

// ============================================================================
extern "C" void kernel_launch(void* const* d_in, const int* in_sizes, int n_in,
                              void* d_out, int out_size)
{
    const float* pc   = (const float*)d_in[0];  // (B,N,3)
    const float* feat = (const float*)d_in[1];  // (B,C,N)
    const float* obj  = (const float*)d_in[2];  // (B,2,N)
    const float* gr   = (const float*)d_in[3];  // (B,N)
    float* out = (float*)d_out;                 // (B,C,M)

    fps_kernel<<<BB, FPS_THREADS>>>(pc, obj, gr);
    nn_kernel<<<(BB * MM) / QPB, NNT>>>(pc);
    interp_kernel<<<(BB * CC * MM + 255) / 256, 256>>>(feat, out);
}

// round 14
// speedup vs baseline: 1.1761x; 1.1183x over previous
#include <cuda_runtime.h>
#include <cstdint>

#define BB 4
#define NPTS 20000
#define CC 512
#define MM 1024
#define GRASP_TH 0.1f

#define FPS_THREADS 512
#define FPS_WARPS (FPS_THREADS / 32)   // 16
#define CAPR 10                        // register-resident points per thread
#define PAIRS (CAPR / 2)               // 5 packed f32x2 pairs
#define REGN (FPS_THREADS * CAPR)      // 5120 register-resident points

// ---------------- scratch (static device allocations; no cudaMalloc) -------
__device__ float4 g_cp[BB * NPTS];    // compacted xyz
__device__ int    g_cidx[BB * NPTS];  // compacted -> original index
__device__ float  g_mind[BB * NPTS];  // FPS min-dist (gmem fallback region only)
__device__ int    g_fps[BB * MM];     // sampled original indices
__device__ int    g_nn[BB * MM * 3];  // 3-NN indices
__device__ float  g_w[BB * MM * 3];   // normalized IDW weights
__device__ float4 g_pc4[BB * NPTS];   // full cloud packed as float4

__device__ __forceinline__ float finf()  { return __int_as_float(0x7f800000); }

// packed f32x2 helpers (Blackwell sm_103a; per-component IEEE rn => bit-exact)
#define ADD2(out, a, b) asm("add.rn.f32x2 %0, %1, %2;" : "=l"(out) : "l"(a), "l"(b))
#define MUL2(out, a, b) asm("mul.rn.f32x2 %0, %1, %2;" : "=l"(out) : "l"(a), "l"(b))
#define PACK2(out, lo, hi) asm("mov.b64 %0, {%1, %2};" : "=l"(out) : "r"(lo), "r"(hi))
#define UNPACK2(lo, hi, in) asm("mov.b64 {%0, %1}, %2;" : "=r"(lo), "=r"(hi) : "l"(in))

// ============================================================================
// Kernel 0: pack full cloud into float4 for LDS.128 in nn_kernel
// ============================================================================
__global__ __launch_bounds__(256)
void pack_kernel(const float* __restrict__ pc)
{
    int e = blockIdx.x * 256 + threadIdx.x;
    if (e < BB * NPTS) {
        const float* p = pc + (size_t)e * 3;
        g_pc4[e] = make_float4(p[0], p[1], p[2], 0.0f);
    }
}

// ============================================================================
// Kernel 1: per-batch mask compaction + furthest point sampling.
// EXACT R6 source (best measured) — do not perturb.
// ============================================================================
__global__ __launch_bounds__(FPS_THREADS, 1)
void fps_kernel(const float* __restrict__ pc,
                const float* __restrict__ obj,
                const float* __restrict__ gr)
{
    const int b    = blockIdx.x;
    const int tid  = threadIdx.x;
    const int lane = tid & 31;
    const int wid  = tid >> 5;

    __shared__ int s_wsum[FPS_WARPS];
    __shared__ int s_base;
    __shared__ unsigned long long s_vi[2][FPS_WARPS];  // (valBits<<32) | ~idx

    if (tid == 0) s_base = 0;
    __syncthreads();

    const float* objb = obj + (size_t)b * 2 * NPTS;
    const float* grb  = gr  + (size_t)b * NPTS;
    const float* pcb  = pc  + (size_t)b * NPTS * 3;

    // ---- order-preserving compaction of masked points ----
    for (int start = 0; start < NPTS; start += FPS_THREADS) {
        int i = start + tid;
        bool p = false;
        if (i < NPTS)
            p = (objb[NPTS + i] > objb[i]) && (grb[i] > GRASP_TH);
        unsigned bal = __ballot_sync(0xffffffffu, p);
        int wcnt = __popc(bal);
        int wpre = __popc(bal & ((1u << lane) - 1u));
        if (lane == 0) s_wsum[wid] = wcnt;
        __syncthreads();
        if (tid == 0) {
            int acc = s_base;
            #pragma unroll
            for (int w = 0; w < FPS_WARPS; ++w) { int c = s_wsum[w]; s_wsum[w] = acc; acc += c; }
            s_base = acc;
        }
        __syncthreads();
        if (p) {
            int pos = s_wsum[wid] + wpre;
            g_cidx[b * NPTS + pos] = i;
            float4 q;
            q.x = pcb[3 * i]; q.y = pcb[3 * i + 1]; q.z = pcb[3 * i + 2]; q.w = 0.0f;
            g_cp[b * NPTS + pos] = q;
        }
        __syncthreads();
    }
    const int cnt = s_base;

    if (cnt == 0) {
        for (int j = tid; j < MM; j += FPS_THREADS) g_fps[b * MM + j] = 0;
        return;
    }

    const float4* cp = g_cp + b * NPTS;
    const int regCnt = min(cnt, REGN);

    // ---- load owned points into packed registers ----
    unsigned long long rx2[PAIRS], ry2[PAIRS], rz2[PAIRS];
    float md[CAPR];
    #pragma unroll
    for (int p = 0; p < PAIRS; ++p) {
        const int k0 = 2 * p, k1 = 2 * p + 1;
        int i0 = tid + k0 * FPS_THREADS;
        int i1 = tid + k1 * FPS_THREADS;
        float x0 = 0.f, y0 = 0.f, z0 = 0.f, x1 = 0.f, y1 = 0.f, z1 = 0.f;
        if (i0 < regCnt) { float4 q = cp[i0]; x0 = q.x; y0 = q.y; z0 = q.z; md[k0] = finf(); }
        else               md[k0] = -0.0f;   // -0: never beats bV>=0 under strict >
        if (i1 < regCnt) { float4 q = cp[i1]; x1 = q.x; y1 = q.y; z1 = q.z; md[k1] = finf(); }
        else               md[k1] = -0.0f;
        PACK2(rx2[p], __float_as_uint(x0), __float_as_uint(x1));
        PACK2(ry2[p], __float_as_uint(y0), __float_as_uint(y1));
        PACK2(rz2[p], __float_as_uint(z0), __float_as_uint(z1));
    }

    // fallback region (cnt > 5120): gmem state
    float* gmind = g_mind + b * NPTS;
    for (int i = REGN + tid; i < cnt; i += FPS_THREADS) gmind[i] = finf();
    __syncthreads();

    // ---- first pick = compacted point 0 ----
    float4 p0 = cp[0];
    float lx = p0.x, ly = p0.y, lz = p0.z;
    if (tid == 0) g_fps[b * MM] = g_cidx[b * NPTS];

    for (int it = 1; it < MM; ++it) {
        const unsigned ph = (unsigned)(it - 1) & 1u;

        unsigned long long nlx2, nly2, nlz2;
        {
            unsigned nx = __float_as_uint(-lx);
            unsigned ny = __float_as_uint(-ly);
            unsigned nz = __float_as_uint(-lz);
            PACK2(nlx2, nx, nx);
            PACK2(nly2, ny, ny);
            PACK2(nlz2, nz, nz);
        }

        float    bV = 0.0f;
        unsigned bI = 0xffffffffu;
        #pragma unroll
        for (int p = 0; p < PAIRS; ++p) {
            unsigned long long dx2, dy2, dz2, s2;
            ADD2(dx2, rx2[p], nlx2);     // dx = rx - lx (exact rn)
            MUL2(dx2, dx2, dx2);
            ADD2(dy2, ry2[p], nly2);
            MUL2(dy2, dy2, dy2);
            ADD2(s2, dx2, dy2);
            ADD2(dz2, rz2[p], nlz2);
            MUL2(dz2, dz2, dz2);
            ADD2(s2, s2, dz2);           // (dx*dx + dy*dy) + dz*dz  -- XLA order
            unsigned dlo, dhi;
            UNPACK2(dlo, dhi, s2);
            float m0 = fminf(md[2 * p],     __uint_as_float(dlo));
            float m1 = fminf(md[2 * p + 1], __uint_as_float(dhi));
            md[2 * p]     = m0;
            md[2 * p + 1] = m1;
            if (m0 > bV) { bV = m0; bI = (unsigned)(tid + (2 * p)     * FPS_THREADS); }
            if (m1 > bV) { bV = m1; bI = (unsigned)(tid + (2 * p + 1) * FPS_THREADS); }
        }
        // fallback region (usually empty)
        for (int i = REGN + tid; i < cnt; i += FPS_THREADS) {
            float4 q = cp[i];
            float dx = q.x - lx;
            float dy = q.y - ly;
            float dz = q.z - lz;
            float d = __fadd_rn(__fadd_rn(__fmul_rn(dx, dx),
                                          __fmul_rn(dy, dy)),
                                __fmul_rn(dz, dz));
            float m = fminf(gmind[i], d);
            gmind[i] = m;
            if (m > bV || (m == bV && (unsigned)i < bI)) { bV = m; bI = (unsigned)i; }
        }

        // --- warp argmax via REDUX (bV >= 0 => f32 bits are u32-monotone) ---
        unsigned vb = __float_as_uint(bV);
        unsigned wv = __reduce_max_sync(0xffffffffu, vb);
        unsigned cand = (vb == wv) ? bI : 0xffffffffu;
        unsigned wi = __reduce_min_sync(0xffffffffu, cand);
        if (vb == wv && bI == wi)        // winning lane(s) write identical value
            s_vi[ph][wid] = ((unsigned long long)wv << 32) | (unsigned)(~wi);
        __syncthreads();

        // --- cross-warp argmax over 16 entries, redundantly in every warp ---
        unsigned long long e = s_vi[ph][lane & (FPS_WARPS - 1)];
        unsigned hv = (unsigned)(e >> 32);
        unsigned lv = (unsigned)e;                  // = ~idx
        unsigned gv = __reduce_max_sync(0xffffffffu, hv);
        unsigned cl = (hv == gv) ? lv : 0u;         // max ~idx == min idx
        unsigned gl = __reduce_max_sync(0xffffffffu, cl);
        unsigned gi = ~gl;
        if (gv == 0u) gi = 0u;   // degenerate: all minds zero -> first masked point

        // --- fetch winner coords: broadcast LDG, L1-resident ---
        float4 w = cp[gi];
        lx = w.x; ly = w.y; lz = w.z;

        if (tid == 0) g_fps[b * MM + it] = g_cidx[b * NPTS + (int)gi];
    }
}

// ============================================================================
// Kernel 2: three_nn — BRANCHLESS key-packed top-3.
// Key = (distBits & 0xFFFF8000) | idx : u32-monotone (dist >= 0), 15-bit
// index in the low bits gives the asc-index tie-break. Insert = 5 IMNMX,
// zero divergence. Distance quantization (8 mantissa bits) perturbs only
// neighbor weights that contribute ~3e-7 of the output (self point w~1).
// Warp serves 4 queries; lane loads each tile point once via LDS.128.
// ============================================================================
#define NNQ 4
#define NNT 256
#define NNW (NNT / 32)
#define QPB (NNW * NNQ)    // 32 queries per block
#define NTS 2048
#define KMASK 0xFFFF8000u
#define IMASK 0x00007FFFu

__device__ __forceinline__ void key_insert(unsigned k, unsigned& k0, unsigned& k1, unsigned& k2)
{
    unsigned n2 = max(k1, min(k2, k));
    unsigned n1 = max(k0, min(k1, k));
    unsigned n0 = min(k0, k);
    k2 = n2; k1 = n1; k0 = n0;
}

__global__ __launch_bounds__(NNT, 1)
void nn_kernel()
{
    __shared__ float4 s_pts[NTS];

    const int tid  = threadIdx.x;
    const int lane = tid & 31;
    const int wid  = tid >> 5;
    const int b    = blockIdx.x / (MM / QPB);
    const int q0   = blockIdx.x * QPB + wid * NNQ;

    const float4* pc4b = g_pc4 + (size_t)b * NPTS;

    float qx[NNQ], qy[NNQ], qz[NNQ];
    #pragma unroll
    for (int t = 0; t < NNQ; ++t) {
        const float4 qp = pc4b[g_fps[q0 + t]];
        qx[t] = qp.x; qy[t] = qp.y; qz[t] = qp.z;
    }

    unsigned k0[NNQ], k1[NNQ], k2[NNQ];
    #pragma unroll
    for (int t = 0; t < NNQ; ++t) { k0[t] = 0xffffffffu; k1[t] = 0xffffffffu; k2[t] = 0xffffffffu; }

    for (int t0 = 0; t0 < NPTS; t0 += NTS) {
        const int ts = min(NTS, NPTS - t0);
        __syncthreads();
        for (int j = tid; j < ts; j += NNT)
            s_pts[j] = pc4b[t0 + j];
        __syncthreads();

        for (int j = lane; j < ts; j += 32) {
            const float4 w = s_pts[j];
            const unsigned gi = (unsigned)(t0 + j);
            #pragma unroll
            for (int t = 0; t < NNQ; ++t) {
                float dx = w.x - qx[t];
                float dy = w.y - qy[t];
                float dz = w.z - qz[t];
                float d = fmaf(dz, dz, fmaf(dy, dy, dx * dx));
                unsigned key = (__float_as_uint(d) & KMASK) | gi;
                key_insert(key, k0[t], k1[t], k2[t]);
            }
        }
    }

    // merge top-3 keys across the 32 lanes, per query
    #pragma unroll
    for (int t = 0; t < NNQ; ++t) {
        #pragma unroll
        for (int off = 16; off; off >>= 1) {
            unsigned o0 = __shfl_down_sync(0xffffffffu, k0[t], off);
            unsigned o1 = __shfl_down_sync(0xffffffffu, k1[t], off);
            unsigned o2 = __shfl_down_sync(0xffffffffu, k2[t], off);
            key_insert(o0, k0[t], k1[t], k2[t]);
            key_insert(o1, k0[t], k1[t], k2[t]);
            key_insert(o2, k0[t], k1[t], k2[t]);
        }
        if (lane == 0) {
            const int q = q0 + t;
            float d0 = __uint_as_float(k0[t] & KMASK);
            float d1 = __uint_as_float(k1[t] & KMASK);
            float d2 = __uint_as_float(k2[t] & KMASK);
            float e0 = sqrtf(fmaxf(d0, 0.0f));
            float e1 = sqrtf(fmaxf(d1, 0.0f));
            float e2 = sqrtf(fmaxf(d2, 0.0f));
            float w0 = 1.0f / (e0 + 1e-8f);
            float w1 = 1.0f / (e1 + 1e-8f);
            float w2 = 1.0f / (e2 + 1e-8f);
            float s  = __fadd_rn(__fadd_rn(w0, w1), w2);
            g_w[3 * q + 0] = w0 / s;
            g_w[3 * q + 1] = w1 / s;
            g_w[3 * q + 2] = w2 / s;
            g_nn[3 * q + 0] = (int)(k0[t] & IMASK);
            g_nn[3 * q + 1] = (int)(k1[t] & IMASK);
            g_nn[3 * q + 2] = (int)(k2[t] & IMASK);
        }
    }
}

// ============================================================================
// Kernel 3: IDW feature interpolation. out[b,c,m] = sum_k w_k * feat[b,c,nn_k]
// ============================================================================
__global__ __launch_bounds__(256)
void interp_kernel(const float* __restrict__ feat, float* __restrict__ out)
{
    int e = blockIdx.x * blockDim.x + threadIdx.x;
    if (e >= BB * CC * MM) return;
    const int m = e % MM;
    const int c = (e / MM) % CC;
    const int b = e / (MM * CC);
    const int q = b * MM + m;

    const int   j0 = g_nn[3 * q],     j1 = g_nn[3 * q + 1], j2 = g_nn[3 * q + 2];
    const float w0 = g_w[3 * q],      w1 = g_w[3 * q + 1],  w2 = g_w[3 * q + 2];
    const float* f = feat + ((size_t)b * CC + c) * NPTS;
    out[e] = w0 * f[j0] + w1 * f[j1] + w2 * f[j2];
}

// ============================================================================
extern "C" void kernel_launch(void* const* d_in, const int* in_sizes, int n_in,
                              void* d_out, int out_size)
{
    const float* pc   = (const float*)d_in[0];  // (B,N,3)
    const float* feat = (const float*)d_in[1];  // (B,C,N)
    const float* obj  = (const float*)d_in[2];  // (B,2,N)
    const float* gr   = (const float*)d_in[3];  // (B,N)
    float* out = (float*)d_out;                 // (B,C,M)

    pack_kernel<<<(BB * NPTS + 255) / 256, 256>>>(pc);
    fps_kernel<<<BB, FPS_THREADS>>>(pc, obj, gr);
    nn_kernel<<<(BB * MM) / QPB, NNT>>>();
    interp_kernel<<<(BB * CC * MM + 255) / 256, 256>>>(feat, out);
}

// round 15
// speedup vs baseline: 1.1847x; 1.0073x over previous
#include <cuda_runtime.h>
#include <cstdint>

#define BB 4
#define NPTS 20000
#define CC 512
#define MM 1024
#define GRASP_TH 0.1f

#define FPS_THREADS 512
#define FPS_WARPS (FPS_THREADS / 32)   // 16
#define CAPR 10                        // register-resident points per thread
#define PAIRS (CAPR / 2)               // 5 packed f32x2 pairs
#define REGN (FPS_THREADS * CAPR)      // 5120 register-resident points

// ---------------- scratch (static device allocations; no cudaMalloc) -------
__device__ float4 g_cp[BB * NPTS];    // compacted xyz
__device__ int    g_cidx[BB * NPTS];  // compacted -> original index
__device__ float  g_mind[BB * NPTS];  // FPS min-dist (gmem fallback region only)
__device__ int    g_fps[BB * MM];     // sampled original indices
__device__ int    g_nn[BB * MM * 3];  // 3-NN indices
__device__ float  g_w[BB * MM * 3];   // normalized IDW weights
__device__ float4 g_pc4[BB * NPTS];   // full cloud packed as float4

__device__ __forceinline__ float finf()  { return __int_as_float(0x7f800000); }

// packed f32x2 helpers (Blackwell sm_103a; per-component IEEE rn => bit-exact)
#define ADD2(out, a, b) asm("add.rn.f32x2 %0, %1, %2;" : "=l"(out) : "l"(a), "l"(b))
#define MUL2(out, a, b) asm("mul.rn.f32x2 %0, %1, %2;" : "=l"(out) : "l"(a), "l"(b))
#define PACK2(out, lo, hi) asm("mov.b64 %0, {%1, %2};" : "=l"(out) : "r"(lo), "r"(hi))
#define UNPACK2(lo, hi, in) asm("mov.b64 {%0, %1}, %2;" : "=r"(lo), "=r"(hi) : "l"(in))

// ============================================================================
// Kernel 0: pack full cloud into float4 for LDS.128 in nn_kernel
// ============================================================================
__global__ __launch_bounds__(256)
void pack_kernel(const float* __restrict__ pc)
{
    int e = blockIdx.x * 256 + threadIdx.x;
    if (e < BB * NPTS) {
        const float* p = pc + (size_t)e * 3;
        g_pc4[e] = make_float4(p[0], p[1], p[2], 0.0f);
    }
}

// ============================================================================
// Kernel 1: per-batch mask compaction + furthest point sampling.
// EXACT R6 source (best measured) — do not perturb.
// ============================================================================
__global__ __launch_bounds__(FPS_THREADS, 1)
void fps_kernel(const float* __restrict__ pc,
                const float* __restrict__ obj,
                const float* __restrict__ gr)
{
    const int b    = blockIdx.x;
    const int tid  = threadIdx.x;
    const int lane = tid & 31;
    const int wid  = tid >> 5;

    __shared__ int s_wsum[FPS_WARPS];
    __shared__ int s_base;
    __shared__ unsigned long long s_vi[2][FPS_WARPS];  // (valBits<<32) | ~idx

    if (tid == 0) s_base = 0;
    __syncthreads();

    const float* objb = obj + (size_t)b * 2 * NPTS;
    const float* grb  = gr  + (size_t)b * NPTS;
    const float* pcb  = pc  + (size_t)b * NPTS * 3;

    // ---- order-preserving compaction of masked points ----
    for (int start = 0; start < NPTS; start += FPS_THREADS) {
        int i = start + tid;
        bool p = false;
        if (i < NPTS)
            p = (objb[NPTS + i] > objb[i]) && (grb[i] > GRASP_TH);
        unsigned bal = __ballot_sync(0xffffffffu, p);
        int wcnt = __popc(bal);
        int wpre = __popc(bal & ((1u << lane) - 1u));
        if (lane == 0) s_wsum[wid] = wcnt;
        __syncthreads();
        if (tid == 0) {
            int acc = s_base;
            #pragma unroll
            for (int w = 0; w < FPS_WARPS; ++w) { int c = s_wsum[w]; s_wsum[w] = acc; acc += c; }
            s_base = acc;
        }
        __syncthreads();
        if (p) {
            int pos = s_wsum[wid] + wpre;
            g_cidx[b * NPTS + pos] = i;
            float4 q;
            q.x = pcb[3 * i]; q.y = pcb[3 * i + 1]; q.z = pcb[3 * i + 2]; q.w = 0.0f;
            g_cp[b * NPTS + pos] = q;
        }
        __syncthreads();
    }
    const int cnt = s_base;

    if (cnt == 0) {
        for (int j = tid; j < MM; j += FPS_THREADS) g_fps[b * MM + j] = 0;
        return;
    }

    const float4* cp = g_cp + b * NPTS;
    const int regCnt = min(cnt, REGN);

    // ---- load owned points into packed registers ----
    unsigned long long rx2[PAIRS], ry2[PAIRS], rz2[PAIRS];
    float md[CAPR];
    #pragma unroll
    for (int p = 0; p < PAIRS; ++p) {
        const int k0 = 2 * p, k1 = 2 * p + 1;
        int i0 = tid + k0 * FPS_THREADS;
        int i1 = tid + k1 * FPS_THREADS;
        float x0 = 0.f, y0 = 0.f, z0 = 0.f, x1 = 0.f, y1 = 0.f, z1 = 0.f;
        if (i0 < regCnt) { float4 q = cp[i0]; x0 = q.x; y0 = q.y; z0 = q.z; md[k0] = finf(); }
        else               md[k0] = -0.0f;   // -0: never beats bV>=0 under strict >
        if (i1 < regCnt) { float4 q = cp[i1]; x1 = q.x; y1 = q.y; z1 = q.z; md[k1] = finf(); }
        else               md[k1] = -0.0f;
        PACK2(rx2[p], __float_as_uint(x0), __float_as_uint(x1));
        PACK2(ry2[p], __float_as_uint(y0), __float_as_uint(y1));
        PACK2(rz2[p], __float_as_uint(z0), __float_as_uint(z1));
    }

    // fallback region (cnt > 5120): gmem state
    float* gmind = g_mind + b * NPTS;
    for (int i = REGN + tid; i < cnt; i += FPS_THREADS) gmind[i] = finf();
    __syncthreads();

    // ---- first pick = compacted point 0 ----
    float4 p0 = cp[0];
    float lx = p0.x, ly = p0.y, lz = p0.z;
    if (tid == 0) g_fps[b * MM] = g_cidx[b * NPTS];

    for (int it = 1; it < MM; ++it) {
        const unsigned ph = (unsigned)(it - 1) & 1u;

        unsigned long long nlx2, nly2, nlz2;
        {
            unsigned nx = __float_as_uint(-lx);
            unsigned ny = __float_as_uint(-ly);
            unsigned nz = __float_as_uint(-lz);
            PACK2(nlx2, nx, nx);
            PACK2(nly2, ny, ny);
            PACK2(nlz2, nz, nz);
        }

        float    bV = 0.0f;
        unsigned bI = 0xffffffffu;
        #pragma unroll
        for (int p = 0; p < PAIRS; ++p) {
            unsigned long long dx2, dy2, dz2, s2;
            ADD2(dx2, rx2[p], nlx2);     // dx = rx - lx (exact rn)
            MUL2(dx2, dx2, dx2);
            ADD2(dy2, ry2[p], nly2);
            MUL2(dy2, dy2, dy2);
            ADD2(s2, dx2, dy2);
            ADD2(dz2, rz2[p], nlz2);
            MUL2(dz2, dz2, dz2);
            ADD2(s2, s2, dz2);           // (dx*dx + dy*dy) + dz*dz  -- XLA order
            unsigned dlo, dhi;
            UNPACK2(dlo, dhi, s2);
            float m0 = fminf(md[2 * p],     __uint_as_float(dlo));
            float m1 = fminf(md[2 * p + 1], __uint_as_float(dhi));
            md[2 * p]     = m0;
            md[2 * p + 1] = m1;
            if (m0 > bV) { bV = m0; bI = (unsigned)(tid + (2 * p)     * FPS_THREADS); }
            if (m1 > bV) { bV = m1; bI = (unsigned)(tid + (2 * p + 1) * FPS_THREADS); }
        }
        // fallback region (usually empty)
        for (int i = REGN + tid; i < cnt; i += FPS_THREADS) {
            float4 q = cp[i];
            float dx = q.x - lx;
            float dy = q.y - ly;
            float dz = q.z - lz;
            float d = __fadd_rn(__fadd_rn(__fmul_rn(dx, dx),
                                          __fmul_rn(dy, dy)),
                                __fmul_rn(dz, dz));
            float m = fminf(gmind[i], d);
            gmind[i] = m;
            if (m > bV || (m == bV && (unsigned)i < bI)) { bV = m; bI = (unsigned)i; }
        }

        // --- warp argmax via REDUX (bV >= 0 => f32 bits are u32-monotone) ---
        unsigned vb = __float_as_uint(bV);
        unsigned wv = __reduce_max_sync(0xffffffffu, vb);
        unsigned cand = (vb == wv) ? bI : 0xffffffffu;
        unsigned wi = __reduce_min_sync(0xffffffffu, cand);
        if (vb == wv && bI == wi)        // winning lane(s) write identical value
            s_vi[ph][wid] = ((unsigned long long)wv << 32) | (unsigned)(~wi);
        __syncthreads();

        // --- cross-warp argmax over 16 entries, redundantly in every warp ---
        unsigned long long e = s_vi[ph][lane & (FPS_WARPS - 1)];
        unsigned hv = (unsigned)(e >> 32);
        unsigned lv = (unsigned)e;                  // = ~idx
        unsigned gv = __reduce_max_sync(0xffffffffu, hv);
        unsigned cl = (hv == gv) ? lv : 0u;         // max ~idx == min idx
        unsigned gl = __reduce_max_sync(0xffffffffu, cl);
        unsigned gi = ~gl;
        if (gv == 0u) gi = 0u;   // degenerate: all minds zero -> first masked point

        // --- fetch winner coords: broadcast LDG, L1-resident ---
        float4 w = cp[gi];
        lx = w.x; ly = w.y; lz = w.z;

        if (tid == 0) g_fps[b * MM + it] = g_cidx[b * NPTS + (int)gi];
    }
}

// ============================================================================
// Kernel 2: three_nn — branchless key-packed top-3 (R14 winner) with
// cp.async DOUBLE-BUFFERED tile pipeline: tile t+1 streams into the spare
// buffer while tile t is consumed, hiding the fill latency that was exposed
// inside the barrier pair. Compute loop and merge unchanged.
// ============================================================================
#define NNQ 4
#define NNT 256
#define NNW (NNT / 32)
#define QPB (NNW * NNQ)    // 32 queries per block
#define NTS 2048
#define NTILES ((NPTS + NTS - 1) / NTS)   // 10
#define KMASK 0xFFFF8000u
#define IMASK 0x00007FFFu

__device__ __forceinline__ void key_insert(unsigned k, unsigned& k0, unsigned& k1, unsigned& k2)
{
    unsigned n2 = max(k1, min(k2, k));
    unsigned n1 = max(k0, min(k1, k));
    unsigned n0 = min(k0, k);
    k2 = n2; k1 = n1; k0 = n0;
}

__device__ __forceinline__ void cp_async16(unsigned smem_addr, const void* gptr)
{
    asm volatile("cp.async.cg.shared.global [%0], [%1], 16;"
                 :: "r"(smem_addr), "l"(gptr) : "memory");
}
__device__ __forceinline__ void cp_commit()
{
    asm volatile("cp.async.commit_group;" ::: "memory");
}
template <int N>
__device__ __forceinline__ void cp_wait()
{
    asm volatile("cp.async.wait_group %0;" :: "n"(N) : "memory");
}

__global__ __launch_bounds__(NNT, 1)
void nn_kernel()
{
    __shared__ float4 s_pts[2][NTS];

    const int tid  = threadIdx.x;
    const int lane = tid & 31;
    const int wid  = tid >> 5;
    const int b    = blockIdx.x / (MM / QPB);
    const int q0   = blockIdx.x * QPB + wid * NNQ;

    const float4* pc4b = g_pc4 + (size_t)b * NPTS;

    float qx[NNQ], qy[NNQ], qz[NNQ];
    #pragma unroll
    for (int t = 0; t < NNQ; ++t) {
        const float4 qp = pc4b[g_fps[q0 + t]];
        qx[t] = qp.x; qy[t] = qp.y; qz[t] = qp.z;
    }

    unsigned k0[NNQ], k1[NNQ], k2[NNQ];
    #pragma unroll
    for (int t = 0; t < NNQ; ++t) { k0[t] = 0xffffffffu; k1[t] = 0xffffffffu; k2[t] = 0xffffffffu; }

    const unsigned sbase0 = (unsigned)__cvta_generic_to_shared(&s_pts[0][0]);
    const unsigned sbase1 = (unsigned)__cvta_generic_to_shared(&s_pts[1][0]);

    // prefetch tile 0 into buffer 0
    {
        const int ts0 = min(NTS, NPTS);
        for (int j = tid; j < ts0; j += NNT)
            cp_async16(sbase0 + j * 16u, pc4b + j);
        cp_commit();
    }

    for (int tl = 0; tl < NTILES; ++tl) {
        const int t0 = tl * NTS;
        const int ts = min(NTS, NPTS - t0);
        const unsigned scur = (tl & 1) ? sbase1 : sbase0;

        // stream next tile into the spare buffer (its previous contents were
        // consumed in iteration tl-1; the barrier below iteration tl-1's
        // compute ordered all reads before these writes)
        if (tl + 1 < NTILES) {
            const int n0 = (tl + 1) * NTS;
            const int nts = min(NTS, NPTS - n0);
            const unsigned snxt = (tl & 1) ? sbase0 : sbase1;
            for (int j = tid; j < nts; j += NNT)
                cp_async16(snxt + j * 16u, pc4b + n0 + j);
            cp_commit();
            cp_wait<1>();   // tile tl's group complete; next may be in flight
        } else {
            cp_wait<0>();
        }
        __syncthreads();    // all threads' fills of tile tl visible block-wide

        const float4* cur = (tl & 1) ? s_pts[1] : s_pts[0];
        for (int j = lane; j < ts; j += 32) {
            const float4 w = cur[j];
            const unsigned gi = (unsigned)(t0 + j);
            #pragma unroll
            for (int t = 0; t < NNQ; ++t) {
                float dx = w.x - qx[t];
                float dy = w.y - qy[t];
                float dz = w.z - qz[t];
                float d = fmaf(dz, dz, fmaf(dy, dy, dx * dx));
                unsigned key = (__float_as_uint(d) & KMASK) | gi;
                key_insert(key, k0[t], k1[t], k2[t]);
            }
        }
        __syncthreads();    // reads of tile tl done before buffer reuse
    }

    // merge top-3 keys across the 32 lanes, per query
    #pragma unroll
    for (int t = 0; t < NNQ; ++t) {
        #pragma unroll
        for (int off = 16; off; off >>= 1) {
            unsigned o0 = __shfl_down_sync(0xffffffffu, k0[t], off);
            unsigned o1 = __shfl_down_sync(0xffffffffu, k1[t], off);
            unsigned o2 = __shfl_down_sync(0xffffffffu, k2[t], off);
            key_insert(o0, k0[t], k1[t], k2[t]);
            key_insert(o1, k0[t], k1[t], k2[t]);
            key_insert(o2, k0[t], k1[t], k2[t]);
        }
        if (lane == 0) {
            const int q = q0 + t;
            float d0 = __uint_as_float(k0[t] & KMASK);
            float d1 = __uint_as_float(k1[t] & KMASK);
            float d2 = __uint_as_float(k2[t] & KMASK);
            float e0 = sqrtf(fmaxf(d0, 0.0f));
            float e1 = sqrtf(fmaxf(d1, 0.0f));
            float e2 = sqrtf(fmaxf(d2, 0.0f));
            float w0 = 1.0f / (e0 + 1e-8f);
            float w1 = 1.0f / (e1 + 1e-8f);
            float w2 = 1.0f / (e2 + 1e-8f);
            float s  = __fadd_rn(__fadd_rn(w0, w1), w2);
            g_w[3 * q + 0] = w0 / s;
            g_w[3 * q + 1] = w1 / s;
            g_w[3 * q + 2] = w2 / s;
            g_nn[3 * q + 0] = (int)(k0[t] & IMASK);
            g_nn[3 * q + 1] = (int)(k1[t] & IMASK);
            g_nn[3 * q + 2] = (int)(k2[t] & IMASK);
        }
    }
}

// ============================================================================
// Kernel 3: IDW feature interpolation. out[b,c,m] = sum_k w_k * feat[b,c,nn_k]
// ============================================================================
__global__ __launch_bounds__(256)
void interp_kernel(const float* __restrict__ feat, float* __restrict__ out)
{
    int e = blockIdx.x * blockDim.x + threadIdx.x;
    if (e >= BB * CC * MM) return;
    const int m = e % MM;
    const int c = (e / MM) % CC;
    const int b = e / (MM * CC);
    const int q = b * MM + m;

    const int   j0 = g_nn[3 * q],     j1 = g_nn[3 * q + 1], j2 = g_nn[3 * q + 2];
    const float w0 = g_w[3 * q],      w1 = g_w[3 * q + 1],  w2 = g_w[3 * q + 2];
    const float* f = feat + ((size_t)b * CC + c) * NPTS;
    out[e] = w0 * f[j0] + w1 * f[j1] + w2 * f[j2];
}

// ============================================================================
extern "C" void kernel_launch(void* const* d_in, const int* in_sizes, int n_in,
                              void* d_out, int out_size)
{
    const float* pc   = (const float*)d_in[0];  // (B,N,3)
    const float* feat = (const float*)d_in[1];  // (B,C,N)
    const float* obj  = (const float*)d_in[2];  // (B,2,N)
    const float* gr   = (const float*)d_in[3];  // (B,N)
    float* out = (float*)d_out;                 // (B,C,M)

    pack_kernel<<<(BB * NPTS + 255) / 256, 256>>>(pc);
    fps_kernel<<<BB, FPS_THREADS>>>(pc, obj, gr);
    nn_kernel<<<(BB * MM) / QPB, NNT>>>();
    interp_kernel<<<(BB * CC * MM + 255) / 256, 256>>>(feat, out);
}

// round 16
// speedup vs baseline: 1.2411x; 1.0476x over previous
#include <cuda_runtime.h>
#include <cstdint>

#define BB 4
#define NPTS 20000
#define CC 512
#define MM 1024
#define GRASP_TH 0.1f

#define FPS_THREADS 512
#define FPS_WARPS (FPS_THREADS / 32)   // 16
#define CAPR 10                        // register-resident points per thread
#define PAIRS (CAPR / 2)               // 5 packed f32x2 pairs
#define REGN (FPS_THREADS * CAPR)      // 5120 register-resident points
#define NCHUNK ((NPTS + FPS_THREADS - 1) / FPS_THREADS)   // 40
#define NGRP ((NCHUNK * FPS_WARPS + 31) / 32)             // 20 scan groups

// ---------------- scratch (static device allocations; no cudaMalloc) -------
__device__ float4 g_cp[BB * NPTS];    // compacted xyz
__device__ int    g_cidx[BB * NPTS];  // compacted -> original index
__device__ float  g_mind[BB * NPTS];  // FPS min-dist (gmem fallback region only)
__device__ int    g_fps[BB * MM];     // sampled original indices
__device__ int    g_nn[BB * MM * 3];  // 3-NN indices
__device__ float  g_w[BB * MM * 3];   // normalized IDW weights
__device__ float4 g_pc4[BB * NPTS];   // full cloud packed as float4

__device__ __forceinline__ float finf()  { return __int_as_float(0x7f800000); }

// packed f32x2 helpers (Blackwell sm_103a; per-component IEEE rn => bit-exact)
#define ADD2(out, a, b) asm("add.rn.f32x2 %0, %1, %2;" : "=l"(out) : "l"(a), "l"(b))
#define MUL2(out, a, b) asm("mul.rn.f32x2 %0, %1, %2;" : "=l"(out) : "l"(a), "l"(b))
#define PACK2(out, lo, hi) asm("mov.b64 %0, {%1, %2};" : "=l"(out) : "r"(lo), "r"(hi))
#define UNPACK2(lo, hi, in) asm("mov.b64 {%0, %1}, %2;" : "=r"(lo), "=r"(hi) : "l"(in))

__device__ __forceinline__ int warp_incl_scan(int x, int lane)
{
    #pragma unroll
    for (int o = 1; o < 32; o <<= 1) {
        int t = __shfl_up_sync(0xffffffffu, x, o);
        if (lane >= o) x += t;
    }
    return x;
}

// ============================================================================
// Kernel 0: pack full cloud into float4 for LDS.128 in nn_kernel
// ============================================================================
__global__ __launch_bounds__(256)
void pack_kernel(const float* __restrict__ pc)
{
    int e = blockIdx.x * 256 + threadIdx.x;
    if (e < BB * NPTS) {
        const float* p = pc + (size_t)e * 3;
        g_pc4[e] = make_float4(p[0], p[1], p[2], 0.0f);
    }
}

// ============================================================================
// Kernel 1: per-batch mask compaction + furthest point sampling.
// Compaction restructured to TWO PASSES with 5 barriers total (was 120):
// pass 1 records 640 per-(chunk,warp) ballot counts barrier-free; one
// hierarchical block scan gives exclusive offsets; pass 2 recomputes the
// predicate (L1-hot) and scatters. Result array byte-identical (order-
// preserving). Register-load phase and MAIN LOOP are byte-identical to the
// best measured kernel — do not perturb.
// ============================================================================
__global__ __launch_bounds__(FPS_THREADS, 1)
void fps_kernel(const float* __restrict__ pc,
                const float* __restrict__ obj,
                const float* __restrict__ gr)
{
    const int b    = blockIdx.x;
    const int tid  = threadIdx.x;
    const int lane = tid & 31;
    const int wid  = tid >> 5;

    __shared__ int s_cnt[NCHUNK * FPS_WARPS];   // counts -> exclusive prefixes
    __shared__ int s_gt[NGRP];                  // scan group totals
    __shared__ int s_base;                      // total masked count
    __shared__ unsigned long long s_vi[2][FPS_WARPS];  // (valBits<<32) | ~idx

    const float* objb = obj + (size_t)b * 2 * NPTS;
    const float* grb  = gr  + (size_t)b * NPTS;
    const float* pcb  = pc  + (size_t)b * NPTS * 3;

    // ---- pass 1: per-(chunk,warp) ballot counts, barrier-free ----
    #pragma unroll 4
    for (int c = 0; c < NCHUNK; ++c) {
        int i = c * FPS_THREADS + tid;
        bool p = false;
        if (i < NPTS)
            p = (objb[NPTS + i] > objb[i]) && (grb[i] > GRASP_TH);
        unsigned bal = __ballot_sync(0xffffffffu, p);
        if (lane == 0) s_cnt[c * FPS_WARPS + wid] = __popc(bal);
    }
    __syncthreads();

    // ---- hierarchical exclusive scan over 640 counts ----
    int v1 = s_cnt[tid];
    int s1 = warp_incl_scan(v1, lane);
    if (lane == 31) s_gt[wid] = s1;             // groups 0..15
    int v2 = 0, s2 = 0;
    if (wid < 4) {                              // tid<128 covers g=512..639
        v2 = s_cnt[FPS_THREADS + tid];
        s2 = warp_incl_scan(v2, lane);
        if (lane == 31) s_gt[16 + wid] = s2;    // groups 16..19
    }
    __syncthreads();
    if (tid < 32) {
        int gv = (tid < NGRP) ? s_gt[tid] : 0;
        int gs = warp_incl_scan(gv, lane);
        if (tid < NGRP) s_gt[tid] = gs - gv;    // exclusive group offsets
        if (tid == NGRP - 1) s_base = gs;       // grand total
    }
    __syncthreads();
    {
        int p1 = s_gt[wid] + s1 - v1;
        int p2 = (wid < 4) ? (s_gt[16 + wid] + s2 - v2) : 0;
        __syncthreads();                        // all reads of s_gt/s_cnt done
        s_cnt[tid] = p1;
        if (wid < 4) s_cnt[FPS_THREADS + tid] = p2;
    }
    __syncthreads();

    // ---- pass 2: recompute predicate (L1-hot) and scatter, barrier-free ----
    #pragma unroll 4
    for (int c = 0; c < NCHUNK; ++c) {
        int i = c * FPS_THREADS + tid;
        bool p = false;
        if (i < NPTS)
            p = (objb[NPTS + i] > objb[i]) && (grb[i] > GRASP_TH);
        unsigned bal = __ballot_sync(0xffffffffu, p);
        if (p) {
            int pos = s_cnt[c * FPS_WARPS + wid] + __popc(bal & ((1u << lane) - 1u));
            g_cidx[b * NPTS + pos] = i;
            float4 q;
            q.x = pcb[3 * i]; q.y = pcb[3 * i + 1]; q.z = pcb[3 * i + 2]; q.w = 0.0f;
            g_cp[b * NPTS + pos] = q;
        }
    }
    __syncthreads();
    const int cnt = s_base;

    if (cnt == 0) {
        for (int j = tid; j < MM; j += FPS_THREADS) g_fps[b * MM + j] = 0;
        return;
    }

    const float4* cp = g_cp + b * NPTS;
    const int regCnt = min(cnt, REGN);

    // ---- load owned points into packed registers ----
    unsigned long long rx2[PAIRS], ry2[PAIRS], rz2[PAIRS];
    float md[CAPR];
    #pragma unroll
    for (int p = 0; p < PAIRS; ++p) {
        const int k0 = 2 * p, k1 = 2 * p + 1;
        int i0 = tid + k0 * FPS_THREADS;
        int i1 = tid + k1 * FPS_THREADS;
        float x0 = 0.f, y0 = 0.f, z0 = 0.f, x1 = 0.f, y1 = 0.f, z1 = 0.f;
        if (i0 < regCnt) { float4 q = cp[i0]; x0 = q.x; y0 = q.y; z0 = q.z; md[k0] = finf(); }
        else               md[k0] = -0.0f;   // -0: never beats bV>=0 under strict >
        if (i1 < regCnt) { float4 q = cp[i1]; x1 = q.x; y1 = q.y; z1 = q.z; md[k1] = finf(); }
        else               md[k1] = -0.0f;
        PACK2(rx2[p], __float_as_uint(x0), __float_as_uint(x1));
        PACK2(ry2[p], __float_as_uint(y0), __float_as_uint(y1));
        PACK2(rz2[p], __float_as_uint(z0), __float_as_uint(z1));
    }

    // fallback region (cnt > 5120): gmem state
    float* gmind = g_mind + b * NPTS;
    for (int i = REGN + tid; i < cnt; i += FPS_THREADS) gmind[i] = finf();
    __syncthreads();

    // ---- first pick = compacted point 0 ----
    float4 p0 = cp[0];
    float lx = p0.x, ly = p0.y, lz = p0.z;
    if (tid == 0) g_fps[b * MM] = g_cidx[b * NPTS];

    for (int it = 1; it < MM; ++it) {
        const unsigned ph = (unsigned)(it - 1) & 1u;

        unsigned long long nlx2, nly2, nlz2;
        {
            unsigned nx = __float_as_uint(-lx);
            unsigned ny = __float_as_uint(-ly);
            unsigned nz = __float_as_uint(-lz);
            PACK2(nlx2, nx, nx);
            PACK2(nly2, ny, ny);
            PACK2(nlz2, nz, nz);
        }

        float    bV = 0.0f;
        unsigned bI = 0xffffffffu;
        #pragma unroll
        for (int p = 0; p < PAIRS; ++p) {
            unsigned long long dx2, dy2, dz2, s2v;
            ADD2(dx2, rx2[p], nlx2);     // dx = rx - lx (exact rn)
            MUL2(dx2, dx2, dx2);
            ADD2(dy2, ry2[p], nly2);
            MUL2(dy2, dy2, dy2);
            ADD2(s2v, dx2, dy2);
            ADD2(dz2, rz2[p], nlz2);
            MUL2(dz2, dz2, dz2);
            ADD2(s2v, s2v, dz2);         // (dx*dx + dy*dy) + dz*dz  -- XLA order
            unsigned dlo, dhi;
            UNPACK2(dlo, dhi, s2v);
            float m0 = fminf(md[2 * p],     __uint_as_float(dlo));
            float m1 = fminf(md[2 * p + 1], __uint_as_float(dhi));
            md[2 * p]     = m0;
            md[2 * p + 1] = m1;
            if (m0 > bV) { bV = m0; bI = (unsigned)(tid + (2 * p)     * FPS_THREADS); }
            if (m1 > bV) { bV = m1; bI = (unsigned)(tid + (2 * p + 1) * FPS_THREADS); }
        }
        // fallback region (usually empty)
        for (int i = REGN + tid; i < cnt; i += FPS_THREADS) {
            float4 q = cp[i];
            float dx = q.x - lx;
            float dy = q.y - ly;
            float dz = q.z - lz;
            float d = __fadd_rn(__fadd_rn(__fmul_rn(dx, dx),
                                          __fmul_rn(dy, dy)),
                                __fmul_rn(dz, dz));
            float m = fminf(gmind[i], d);
            gmind[i] = m;
            if (m > bV || (m == bV && (unsigned)i < bI)) { bV = m; bI = (unsigned)i; }
        }

        // --- warp argmax via REDUX (bV >= 0 => f32 bits are u32-monotone) ---
        unsigned vb = __float_as_uint(bV);
        unsigned wv = __reduce_max_sync(0xffffffffu, vb);
        unsigned cand = (vb == wv) ? bI : 0xffffffffu;
        unsigned wi = __reduce_min_sync(0xffffffffu, cand);
        if (vb == wv && bI == wi)        // winning lane(s) write identical value
            s_vi[ph][wid] = ((unsigned long long)wv << 32) | (unsigned)(~wi);
        __syncthreads();

        // --- cross-warp argmax over 16 entries, redundantly in every warp ---
        unsigned long long e = s_vi[ph][lane & (FPS_WARPS - 1)];
        unsigned hv = (unsigned)(e >> 32);
        unsigned lv = (unsigned)e;                  // = ~idx
        unsigned gv = __reduce_max_sync(0xffffffffu, hv);
        unsigned cl = (hv == gv) ? lv : 0u;         // max ~idx == min idx
        unsigned gl = __reduce_max_sync(0xffffffffu, cl);
        unsigned gi = ~gl;
        if (gv == 0u) gi = 0u;   // degenerate: all minds zero -> first masked point

        // --- fetch winner coords: broadcast LDG, L1-resident ---
        float4 w = cp[gi];
        lx = w.x; ly = w.y; lz = w.z;

        if (tid == 0) g_fps[b * MM + it] = g_cidx[b * NPTS + (int)gi];
    }
}

// ============================================================================
// Kernel 2: three_nn — branchless key-packed top-3 with cp.async
// double-buffered tile pipeline (best measured). Unchanged.
// ============================================================================
#define NNQ 4
#define NNT 256
#define NNW (NNT / 32)
#define QPB (NNW * NNQ)    // 32 queries per block
#define NTS 2048
#define NTILES ((NPTS + NTS - 1) / NTS)   // 10
#define KMASK 0xFFFF8000u
#define IMASK 0x00007FFFu

__device__ __forceinline__ void key_insert(unsigned k, unsigned& k0, unsigned& k1, unsigned& k2)
{
    unsigned n2 = max(k1, min(k2, k));
    unsigned n1 = max(k0, min(k1, k));
    unsigned n0 = min(k0, k);
    k2 = n2; k1 = n1; k0 = n0;
}

__device__ __forceinline__ void cp_async16(unsigned smem_addr, const void* gptr)
{
    asm volatile("cp.async.cg.shared.global [%0], [%1], 16;"
                 :: "r"(smem_addr), "l"(gptr) : "memory");
}
__device__ __forceinline__ void cp_commit()
{
    asm volatile("cp.async.commit_group;" ::: "memory");
}
template <int N>
__device__ __forceinline__ void cp_wait()
{
    asm volatile("cp.async.wait_group %0;" :: "n"(N) : "memory");
}

__global__ __launch_bounds__(NNT, 1)
void nn_kernel()
{
    __shared__ float4 s_pts[2][NTS];

    const int tid  = threadIdx.x;
    const int lane = tid & 31;
    const int wid  = tid >> 5;
    const int b    = blockIdx.x / (MM / QPB);
    const int q0   = blockIdx.x * QPB + wid * NNQ;

    const float4* pc4b = g_pc4 + (size_t)b * NPTS;

    float qx[NNQ], qy[NNQ], qz[NNQ];
    #pragma unroll
    for (int t = 0; t < NNQ; ++t) {
        const float4 qp = pc4b[g_fps[q0 + t]];
        qx[t] = qp.x; qy[t] = qp.y; qz[t] = qp.z;
    }

    unsigned k0[NNQ], k1[NNQ], k2[NNQ];
    #pragma unroll
    for (int t = 0; t < NNQ; ++t) { k0[t] = 0xffffffffu; k1[t] = 0xffffffffu; k2[t] = 0xffffffffu; }

    const unsigned sbase0 = (unsigned)__cvta_generic_to_shared(&s_pts[0][0]);
    const unsigned sbase1 = (unsigned)__cvta_generic_to_shared(&s_pts[1][0]);

    // prefetch tile 0 into buffer 0
    {
        const int ts0 = min(NTS, NPTS);
        for (int j = tid; j < ts0; j += NNT)
            cp_async16(sbase0 + j * 16u, pc4b + j);
        cp_commit();
    }

    for (int tl = 0; tl < NTILES; ++tl) {
        const int t0 = tl * NTS;
        const int ts = min(NTS, NPTS - t0);

        if (tl + 1 < NTILES) {
            const int n0 = (tl + 1) * NTS;
            const int nts = min(NTS, NPTS - n0);
            const unsigned snxt = (tl & 1) ? sbase0 : sbase1;
            for (int j = tid; j < nts; j += NNT)
                cp_async16(snxt + j * 16u, pc4b + n0 + j);
            cp_commit();
            cp_wait<1>();   // tile tl's group complete; next may be in flight
        } else {
            cp_wait<0>();
        }
        __syncthreads();    // all threads' fills of tile tl visible block-wide

        const float4* cur = (tl & 1) ? s_pts[1] : s_pts[0];
        for (int j = lane; j < ts; j += 32) {
            const float4 w = cur[j];
            const unsigned gi = (unsigned)(t0 + j);
            #pragma unroll
            for (int t = 0; t < NNQ; ++t) {
                float dx = w.x - qx[t];
                float dy = w.y - qy[t];
                float dz = w.z - qz[t];
                float d = fmaf(dz, dz, fmaf(dy, dy, dx * dx));
                unsigned key = (__float_as_uint(d) & KMASK) | gi;
                key_insert(key, k0[t], k1[t], k2[t]);
            }
        }
        __syncthreads();    // reads of tile tl done before buffer reuse
    }

    // merge top-3 keys across the 32 lanes, per query
    #pragma unroll
    for (int t = 0; t < NNQ; ++t) {
        #pragma unroll
        for (int off = 16; off; off >>= 1) {
            unsigned o0 = __shfl_down_sync(0xffffffffu, k0[t], off);
            unsigned o1 = __shfl_down_sync(0xffffffffu, k1[t], off);
            unsigned o2 = __shfl_down_sync(0xffffffffu, k2[t], off);
            key_insert(o0, k0[t], k1[t], k2[t]);
            key_insert(o1, k0[t], k1[t], k2[t]);
            key_insert(o2, k0[t], k1[t], k2[t]);
        }
        if (lane == 0) {
            const int q = q0 + t;
            float d0 = __uint_as_float(k0[t] & KMASK);
            float d1 = __uint_as_float(k1[t] & KMASK);
            float d2 = __uint_as_float(k2[t] & KMASK);
            float e0 = sqrtf(fmaxf(d0, 0.0f));
            float e1 = sqrtf(fmaxf(d1, 0.0f));
            float e2 = sqrtf(fmaxf(d2, 0.0f));
            float w0 = 1.0f / (e0 + 1e-8f);
            float w1 = 1.0f / (e1 + 1e-8f);
            float w2 = 1.0f / (e2 + 1e-8f);
            float s  = __fadd_rn(__fadd_rn(w0, w1), w2);
            g_w[3 * q + 0] = w0 / s;
            g_w[3 * q + 1] = w1 / s;
            g_w[3 * q + 2] = w2 / s;
            g_nn[3 * q + 0] = (int)(k0[t] & IMASK);
            g_nn[3 * q + 1] = (int)(k1[t] & IMASK);
            g_nn[3 * q + 2] = (int)(k2[t] & IMASK);
        }
    }
}

// ============================================================================
// Kernel 3: IDW feature interpolation. out[b,c,m] = sum_k w_k * feat[b,c,nn_k]
// ============================================================================
__global__ __launch_bounds__(256)
void interp_kernel(const float* __restrict__ feat, float* __restrict__ out)
{
    int e = blockIdx.x * blockDim.x + threadIdx.x;
    if (e >= BB * CC * MM) return;
    const int m = e % MM;
    const int c = (e / MM) % CC;
    const int b = e / (MM * CC);
    const int q = b * MM + m;

    const int   j0 = g_nn[3 * q],     j1 = g_nn[3 * q + 1], j2 = g_nn[3 * q + 2];
    const float w0 = g_w[3 * q],      w1 = g_w[3 * q + 1],  w2 = g_w[3 * q + 2];
    const float* f = feat + ((size_t)b * CC + c) * NPTS;
    out[e] = w0 * f[j0] + w1 * f[j1] + w2 * f[j2];
}

// ============================================================================
extern "C" void kernel_launch(void* const* d_in, const int* in_sizes, int n_in,
                              void* d_out, int out_size)
{
    const float* pc   = (const float*)d_in[0];  // (B,N,3)
    const float* feat = (const float*)d_in[1];  // (B,C,N)
    const float* obj  = (const float*)d_in[2];  // (B,2,N)
    const float* gr   = (const float*)d_in[3];  // (B,N)
    float* out = (float*)d_out;                 // (B,C,M)

    pack_kernel<<<(BB * NPTS + 255) / 256, 256>>>(pc);
    fps_kernel<<<BB, FPS_THREADS>>>(pc, obj, gr);
    nn_kernel<<<(BB * MM) / QPB, NNT>>>();
    interp_kernel<<<(BB * CC * MM + 255) / 256, 256>>>(feat, out);
}

// round 17
// speedup vs baseline: 1.2557x; 1.0117x over previous
#include <cuda_runtime.h>
#include <cstdint>

#define BB 4
#define NPTS 20000
#define CC 512
#define MM 1024
#define GRASP_TH 0.1f

#define FPS_THREADS 512
#define FPS_WARPS (FPS_THREADS / 32)   // 16
#define CAPR 10                        // register-resident points per thread
#define PAIRS (CAPR / 2)               // 5 packed f32x2 pairs
#define REGN (FPS_THREADS * CAPR)      // 5120 register-resident points
#define NCHUNK ((NPTS + FPS_THREADS - 1) / FPS_THREADS)   // 40
#define NGRP ((NCHUNK * FPS_WARPS + 31) / 32)             // 20 scan groups

// ---------------- scratch (static device allocations; no cudaMalloc) -------
__device__ float4 g_cp[BB * NPTS];    // compacted xyz
__device__ int    g_cidx[BB * NPTS];  // compacted -> original index
__device__ float  g_mind[BB * NPTS];  // FPS min-dist (gmem fallback region only)
__device__ int    g_fps[BB * MM];     // sampled original indices
__device__ int    g_nn[BB * MM * 3];  // 3-NN indices
__device__ float  g_w[BB * MM * 3];   // normalized IDW weights
__device__ float4 g_pc4[BB * NPTS];   // full cloud packed as float4

__device__ __forceinline__ float finf()  { return __int_as_float(0x7f800000); }

// packed f32x2 helpers (Blackwell sm_103a; per-component IEEE rn => bit-exact)
#define ADD2(out, a, b) asm("add.rn.f32x2 %0, %1, %2;" : "=l"(out) : "l"(a), "l"(b))
#define MUL2(out, a, b) asm("mul.rn.f32x2 %0, %1, %2;" : "=l"(out) : "l"(a), "l"(b))
#define FMA2(out, a, b, c) asm("fma.rn.f32x2 %0, %1, %2, %3;" : "=l"(out) : "l"(a), "l"(b), "l"(c))
#define PACK2(out, lo, hi) asm("mov.b64 %0, {%1, %2};" : "=l"(out) : "r"(lo), "r"(hi))
#define UNPACK2(lo, hi, in) asm("mov.b64 {%0, %1}, %2;" : "=r"(lo), "=r"(hi) : "l"(in))

__device__ __forceinline__ int warp_incl_scan(int x, int lane)
{
    #pragma unroll
    for (int o = 1; o < 32; o <<= 1) {
        int t = __shfl_up_sync(0xffffffffu, x, o);
        if (lane >= o) x += t;
    }
    return x;
}

// ============================================================================
// Kernel 0: pack full cloud into float4 for LDS.128 in nn_kernel
// ============================================================================
__global__ __launch_bounds__(256)
void pack_kernel(const float* __restrict__ pc)
{
    int e = blockIdx.x * 256 + threadIdx.x;
    if (e < BB * NPTS) {
        const float* p = pc + (size_t)e * 3;
        g_pc4[e] = make_float4(p[0], p[1], p[2], 0.0f);
    }
}

// ============================================================================
// Kernel 1: per-batch mask compaction + furthest point sampling.
// BYTE-IDENTICAL to the R16 best-measured kernel (538us) — do not perturb.
// ============================================================================
__global__ __launch_bounds__(FPS_THREADS, 1)
void fps_kernel(const float* __restrict__ pc,
                const float* __restrict__ obj,
                const float* __restrict__ gr)
{
    const int b    = blockIdx.x;
    const int tid  = threadIdx.x;
    const int lane = tid & 31;
    const int wid  = tid >> 5;

    __shared__ int s_cnt[NCHUNK * FPS_WARPS];   // counts -> exclusive prefixes
    __shared__ int s_gt[NGRP];                  // scan group totals
    __shared__ int s_base;                      // total masked count
    __shared__ unsigned long long s_vi[2][FPS_WARPS];  // (valBits<<32) | ~idx

    const float* objb = obj + (size_t)b * 2 * NPTS;
    const float* grb  = gr  + (size_t)b * NPTS;
    const float* pcb  = pc  + (size_t)b * NPTS * 3;

    // ---- pass 1: per-(chunk,warp) ballot counts, barrier-free ----
    #pragma unroll 4
    for (int c = 0; c < NCHUNK; ++c) {
        int i = c * FPS_THREADS + tid;
        bool p = false;
        if (i < NPTS)
            p = (objb[NPTS + i] > objb[i]) && (grb[i] > GRASP_TH);
        unsigned bal = __ballot_sync(0xffffffffu, p);
        if (lane == 0) s_cnt[c * FPS_WARPS + wid] = __popc(bal);
    }
    __syncthreads();

    // ---- hierarchical exclusive scan over 640 counts ----
    int v1 = s_cnt[tid];
    int s1 = warp_incl_scan(v1, lane);
    if (lane == 31) s_gt[wid] = s1;             // groups 0..15
    int v2 = 0, s2 = 0;
    if (wid < 4) {                              // tid<128 covers g=512..639
        v2 = s_cnt[FPS_THREADS + tid];
        s2 = warp_incl_scan(v2, lane);
        if (lane == 31) s_gt[16 + wid] = s2;    // groups 16..19
    }
    __syncthreads();
    if (tid < 32) {
        int gv = (tid < NGRP) ? s_gt[tid] : 0;
        int gs = warp_incl_scan(gv, lane);
        if (tid < NGRP) s_gt[tid] = gs - gv;    // exclusive group offsets
        if (tid == NGRP - 1) s_base = gs;       // grand total
    }
    __syncthreads();
    {
        int p1 = s_gt[wid] + s1 - v1;
        int p2 = (wid < 4) ? (s_gt[16 + wid] + s2 - v2) : 0;
        __syncthreads();                        // all reads of s_gt/s_cnt done
        s_cnt[tid] = p1;
        if (wid < 4) s_cnt[FPS_THREADS + tid] = p2;
    }
    __syncthreads();

    // ---- pass 2: recompute predicate (L1-hot) and scatter, barrier-free ----
    #pragma unroll 4
    for (int c = 0; c < NCHUNK; ++c) {
        int i = c * FPS_THREADS + tid;
        bool p = false;
        if (i < NPTS)
            p = (objb[NPTS + i] > objb[i]) && (grb[i] > GRASP_TH);
        unsigned bal = __ballot_sync(0xffffffffu, p);
        if (p) {
            int pos = s_cnt[c * FPS_WARPS + wid] + __popc(bal & ((1u << lane) - 1u));
            g_cidx[b * NPTS + pos] = i;
            float4 q;
            q.x = pcb[3 * i]; q.y = pcb[3 * i + 1]; q.z = pcb[3 * i + 2]; q.w = 0.0f;
            g_cp[b * NPTS + pos] = q;
        }
    }
    __syncthreads();
    const int cnt = s_base;

    if (cnt == 0) {
        for (int j = tid; j < MM; j += FPS_THREADS) g_fps[b * MM + j] = 0;
        return;
    }

    const float4* cp = g_cp + b * NPTS;
    const int regCnt = min(cnt, REGN);

    // ---- load owned points into packed registers ----
    unsigned long long rx2[PAIRS], ry2[PAIRS], rz2[PAIRS];
    float md[CAPR];
    #pragma unroll
    for (int p = 0; p < PAIRS; ++p) {
        const int k0 = 2 * p, k1 = 2 * p + 1;
        int i0 = tid + k0 * FPS_THREADS;
        int i1 = tid + k1 * FPS_THREADS;
        float x0 = 0.f, y0 = 0.f, z0 = 0.f, x1 = 0.f, y1 = 0.f, z1 = 0.f;
        if (i0 < regCnt) { float4 q = cp[i0]; x0 = q.x; y0 = q.y; z0 = q.z; md[k0] = finf(); }
        else               md[k0] = -0.0f;   // -0: never beats bV>=0 under strict >
        if (i1 < regCnt) { float4 q = cp[i1]; x1 = q.x; y1 = q.y; z1 = q.z; md[k1] = finf(); }
        else               md[k1] = -0.0f;
        PACK2(rx2[p], __float_as_uint(x0), __float_as_uint(x1));
        PACK2(ry2[p], __float_as_uint(y0), __float_as_uint(y1));
        PACK2(rz2[p], __float_as_uint(z0), __float_as_uint(z1));
    }

    // fallback region (cnt > 5120): gmem state
    float* gmind = g_mind + b * NPTS;
    for (int i = REGN + tid; i < cnt; i += FPS_THREADS) gmind[i] = finf();
    __syncthreads();

    // ---- first pick = compacted point 0 ----
    float4 p0 = cp[0];
    float lx = p0.x, ly = p0.y, lz = p0.z;
    if (tid == 0) g_fps[b * MM] = g_cidx[b * NPTS];

    for (int it = 1; it < MM; ++it) {
        const unsigned ph = (unsigned)(it - 1) & 1u;

        unsigned long long nlx2, nly2, nlz2;
        {
            unsigned nx = __float_as_uint(-lx);
            unsigned ny = __float_as_uint(-ly);
            unsigned nz = __float_as_uint(-lz);
            PACK2(nlx2, nx, nx);
            PACK2(nly2, ny, ny);
            PACK2(nlz2, nz, nz);
        }

        float    bV = 0.0f;
        unsigned bI = 0xffffffffu;
        #pragma unroll
        for (int p = 0; p < PAIRS; ++p) {
            unsigned long long dx2, dy2, dz2, s2v;
            ADD2(dx2, rx2[p], nlx2);     // dx = rx - lx (exact rn)
            MUL2(dx2, dx2, dx2);
            ADD2(dy2, ry2[p], nly2);
            MUL2(dy2, dy2, dy2);
            ADD2(s2v, dx2, dy2);
            ADD2(dz2, rz2[p], nlz2);
            MUL2(dz2, dz2, dz2);
            ADD2(s2v, s2v, dz2);         // (dx*dx + dy*dy) + dz*dz  -- XLA order
            unsigned dlo, dhi;
            UNPACK2(dlo, dhi, s2v);
            float m0 = fminf(md[2 * p],     __uint_as_float(dlo));
            float m1 = fminf(md[2 * p + 1], __uint_as_float(dhi));
            md[2 * p]     = m0;
            md[2 * p + 1] = m1;
            if (m0 > bV) { bV = m0; bI = (unsigned)(tid + (2 * p)     * FPS_THREADS); }
            if (m1 > bV) { bV = m1; bI = (unsigned)(tid + (2 * p + 1) * FPS_THREADS); }
        }
        // fallback region (usually empty)
        for (int i = REGN + tid; i < cnt; i += FPS_THREADS) {
            float4 q = cp[i];
            float dx = q.x - lx;
            float dy = q.y - ly;
            float dz = q.z - lz;
            float d = __fadd_rn(__fadd_rn(__fmul_rn(dx, dx),
                                          __fmul_rn(dy, dy)),
                                __fmul_rn(dz, dz));
            float m = fminf(gmind[i], d);
            gmind[i] = m;
            if (m > bV || (m == bV && (unsigned)i < bI)) { bV = m; bI = (unsigned)i; }
        }

        // --- warp argmax via REDUX (bV >= 0 => f32 bits are u32-monotone) ---
        unsigned vb = __float_as_uint(bV);
        unsigned wv = __reduce_max_sync(0xffffffffu, vb);
        unsigned cand = (vb == wv) ? bI : 0xffffffffu;
        unsigned wi = __reduce_min_sync(0xffffffffu, cand);
        if (vb == wv && bI == wi)        // winning lane(s) write identical value
            s_vi[ph][wid] = ((unsigned long long)wv << 32) | (unsigned)(~wi);
        __syncthreads();

        // --- cross-warp argmax over 16 entries, redundantly in every warp ---
        unsigned long long e = s_vi[ph][lane & (FPS_WARPS - 1)];
        unsigned hv = (unsigned)(e >> 32);
        unsigned lv = (unsigned)e;                  // = ~idx
        unsigned gv = __reduce_max_sync(0xffffffffu, hv);
        unsigned cl = (hv == gv) ? lv : 0u;         // max ~idx == min idx
        unsigned gl = __reduce_max_sync(0xffffffffu, cl);
        unsigned gi = ~gl;
        if (gv == 0u) gi = 0u;   // degenerate: all minds zero -> first masked point

        // --- fetch winner coords: broadcast LDG, L1-resident ---
        float4 w = cp[gi];
        lx = w.x; ly = w.y; lz = w.z;

        if (tid == 0) g_fps[b * MM + it] = g_cidx[b * NPTS + (int)gi];
    }
}

// ============================================================================
// Kernel 2: three_nn — branchless key-packed top-3, cp.async double-buffered.
// NEW: distances computed with packed f32x2 over QUERY PAIRS (fma.rn.f32x2):
// 6 packed ops cover 2 queries (3/query vs 6 scalar). Key = LOP3-fused
// (distBits & KMASK) | idx; insert = 5 IMNMX (unchanged R14/R15 semantics).
// ============================================================================
#define NNQ 4
#define NNT 256
#define NNW (NNT / 32)
#define QPB (NNW * NNQ)    // 32 queries per block
#define NTS 2048
#define NTILES ((NPTS + NTS - 1) / NTS)   // 10
#define KMASK 0xFFFF8000u
#define IMASK 0x00007FFFu

__device__ __forceinline__ void key_insert(unsigned k, unsigned& k0, unsigned& k1, unsigned& k2)
{
    unsigned n2 = max(k1, min(k2, k));
    unsigned n1 = max(k0, min(k1, k));
    unsigned n0 = min(k0, k);
    k2 = n2; k1 = n1; k0 = n0;
}

__device__ __forceinline__ void cp_async16(unsigned smem_addr, const void* gptr)
{
    asm volatile("cp.async.cg.shared.global [%0], [%1], 16;"
                 :: "r"(smem_addr), "l"(gptr) : "memory");
}
__device__ __forceinline__ void cp_commit()
{
    asm volatile("cp.async.commit_group;" ::: "memory");
}
template <int N>
__device__ __forceinline__ void cp_wait()
{
    asm volatile("cp.async.wait_group %0;" :: "n"(N) : "memory");
}

__global__ __launch_bounds__(NNT, 1)
void nn_kernel()
{
    __shared__ float4 s_pts[2][NTS];

    const int tid  = threadIdx.x;
    const int lane = tid & 31;
    const int wid  = tid >> 5;
    const int b    = blockIdx.x / (MM / QPB);
    const int q0   = blockIdx.x * QPB + wid * NNQ;

    const float4* pc4b = g_pc4 + (size_t)b * NPTS;

    // negated query coords, packed per query-pair: h=0 -> queries 0,1; h=1 -> 2,3
    unsigned long long nqx2[2], nqy2[2], nqz2[2];
    #pragma unroll
    for (int h = 0; h < 2; ++h) {
        const float4 qa = pc4b[g_fps[q0 + 2 * h]];
        const float4 qb = pc4b[g_fps[q0 + 2 * h + 1]];
        PACK2(nqx2[h], __float_as_uint(-qa.x), __float_as_uint(-qb.x));
        PACK2(nqy2[h], __float_as_uint(-qa.y), __float_as_uint(-qb.y));
        PACK2(nqz2[h], __float_as_uint(-qa.z), __float_as_uint(-qb.z));
    }

    unsigned k0[NNQ], k1[NNQ], k2[NNQ];
    #pragma unroll
    for (int t = 0; t < NNQ; ++t) { k0[t] = 0xffffffffu; k1[t] = 0xffffffffu; k2[t] = 0xffffffffu; }

    const unsigned sbase0 = (unsigned)__cvta_generic_to_shared(&s_pts[0][0]);
    const unsigned sbase1 = (unsigned)__cvta_generic_to_shared(&s_pts[1][0]);

    // prefetch tile 0 into buffer 0
    {
        const int ts0 = min(NTS, NPTS);
        for (int j = tid; j < ts0; j += NNT)
            cp_async16(sbase0 + j * 16u, pc4b + j);
        cp_commit();
    }

    for (int tl = 0; tl < NTILES; ++tl) {
        const int t0 = tl * NTS;
        const int ts = min(NTS, NPTS - t0);

        if (tl + 1 < NTILES) {
            const int n0 = (tl + 1) * NTS;
            const int nts = min(NTS, NPTS - n0);
            const unsigned snxt = (tl & 1) ? sbase0 : sbase1;
            for (int j = tid; j < nts; j += NNT)
                cp_async16(snxt + j * 16u, pc4b + n0 + j);
            cp_commit();
            cp_wait<1>();   // tile tl's group complete; next may be in flight
        } else {
            cp_wait<0>();
        }
        __syncthreads();    // all threads' fills of tile tl visible block-wide

        const float4* cur = (tl & 1) ? s_pts[1] : s_pts[0];
        for (int j = lane; j < ts; j += 32) {
            const float4 w = cur[j];
            const unsigned gi = (unsigned)(t0 + j);
            // broadcast point coords into packed form (shared by both pairs)
            unsigned long long wx2, wy2, wz2;
            {
                unsigned xb = __float_as_uint(w.x);
                unsigned yb = __float_as_uint(w.y);
                unsigned zb = __float_as_uint(w.z);
                PACK2(wx2, xb, xb);
                PACK2(wy2, yb, yb);
                PACK2(wz2, zb, zb);
            }
            #pragma unroll
            for (int h = 0; h < 2; ++h) {
                unsigned long long dx2, dy2, dz2, s2;
                ADD2(dx2, wx2, nqx2[h]);
                ADD2(dy2, wy2, nqy2[h]);
                ADD2(dz2, wz2, nqz2[h]);
                MUL2(s2, dx2, dx2);
                FMA2(s2, dy2, dy2, s2);
                FMA2(s2, dz2, dz2, s2);
                unsigned dlo, dhi;
                UNPACK2(dlo, dhi, s2);
                unsigned keyA = (dlo & KMASK) | gi;
                unsigned keyB = (dhi & KMASK) | gi;
                key_insert(keyA, k0[2 * h],     k1[2 * h],     k2[2 * h]);
                key_insert(keyB, k0[2 * h + 1], k1[2 * h + 1], k2[2 * h + 1]);
            }
        }
        __syncthreads();    // reads of tile tl done before buffer reuse
    }

    // merge top-3 keys across the 32 lanes, per query
    #pragma unroll
    for (int t = 0; t < NNQ; ++t) {
        #pragma unroll
        for (int off = 16; off; off >>= 1) {
            unsigned o0 = __shfl_down_sync(0xffffffffu, k0[t], off);
            unsigned o1 = __shfl_down_sync(0xffffffffu, k1[t], off);
            unsigned o2 = __shfl_down_sync(0xffffffffu, k2[t], off);
            key_insert(o0, k0[t], k1[t], k2[t]);
            key_insert(o1, k0[t], k1[t], k2[t]);
            key_insert(o2, k0[t], k1[t], k2[t]);
        }
        if (lane == 0) {
            const int q = q0 + t;
            float d0 = __uint_as_float(k0[t] & KMASK);
            float d1 = __uint_as_float(k1[t] & KMASK);
            float d2 = __uint_as_float(k2[t] & KMASK);
            float e0 = sqrtf(fmaxf(d0, 0.0f));
            float e1 = sqrtf(fmaxf(d1, 0.0f));
            float e2 = sqrtf(fmaxf(d2, 0.0f));
            float w0 = 1.0f / (e0 + 1e-8f);
            float w1 = 1.0f / (e1 + 1e-8f);
            float w2 = 1.0f / (e2 + 1e-8f);
            float s  = __fadd_rn(__fadd_rn(w0, w1), w2);
            g_w[3 * q + 0] = w0 / s;
            g_w[3 * q + 1] = w1 / s;
            g_w[3 * q + 2] = w2 / s;
            g_nn[3 * q + 0] = (int)(k0[t] & IMASK);
            g_nn[3 * q + 1] = (int)(k1[t] & IMASK);
            g_nn[3 * q + 2] = (int)(k2[t] & IMASK);
        }
    }
}

// ============================================================================
// Kernel 3: IDW feature interpolation. out[b,c,m] = sum_k w_k * feat[b,c,nn_k]
// ============================================================================
__global__ __launch_bounds__(256)
void interp_kernel(const float* __restrict__ feat, float* __restrict__ out)
{
    int e = blockIdx.x * blockDim.x + threadIdx.x;
    if (e >= BB * CC * MM) return;
    const int m = e % MM;
    const int c = (e / MM) % CC;
    const int b = e / (MM * CC);
    const int q = b * MM + m;

    const int   j0 = g_nn[3 * q],     j1 = g_nn[3 * q + 1], j2 = g_nn[3 * q + 2];
    const float w0 = g_w[3 * q],      w1 = g_w[3 * q + 1],  w2 = g_w[3 * q + 2];
    const float* f = feat + ((size_t)b * CC + c) * NPTS;
    out[e] = w0 * f[j0] + w1 * f[j1] + w2 * f[j2];
}

// ============================================================================
extern "C" void kernel_launch(void* const* d_in, const int* in_sizes, int n_in,
                              void* d_out, int out_size)
{
    const float* pc   = (const float*)d_in[0];  // (B,N,3)
    const float* feat = (const float*)d_in[1];  // (B,C,N)
    const float* obj  = (const float*)d_in[2];  // (B,2,N)
    const float* gr   = (const float*)d_in[3];  // (B,N)
    float* out = (float*)d_out;                 // (B,C,M)

    pack_kernel<<<(BB * NPTS + 255) / 256, 256>>>(pc);
    fps_kernel<<<BB, FPS_THREADS>>>(pc, obj, gr);
    nn_kernel<<<(BB * MM) / QPB, NNT>>>();
    interp_kernel<<<(BB * CC * MM + 255) / 256, 256>>>(feat, out);
}